// round 6
// baseline (speedup 1.0000x reference)
#include <cuda_runtime.h>
#include <math.h>

// ---------------- problem constants ----------------
#define NGT   100000
#define NAG   20000
#define EGT   640000
#define ECM   320000
#define DGT   32
#define DAG   64
#define VIS   64
#define CMM   128
#define MSG   64
#define OUTD  5
#define NH    4
#define FSW   192      // fused fs width: [fs1(64) | fs2(128)]
#define HYW   192      // [h(128) | y(64)]

// ---------------- scratch (device globals) ----------------
__device__ __align__(128) float g_fs12[(size_t)NGT * FSW];
__device__ __align__(128) float g_el1[NGT * NH];
__device__ __align__(128) float g_el2[NGT * NH];
__device__ __align__(128) float g_er1[NAG * NH];
__device__ __align__(128) float g_er2[NAG * NH];
__device__ __align__(128) float g_dst2[NAG * CMM];   // [h_vis1 | feat_agent]
__device__ __align__(128) float g_hy[(size_t)NAG * HYW];
__device__ __align__(128) float g_t128[NAG * CMM];
__device__ __align__(128) float g_m[NAG * MSG];
__device__ __align__(128) float g_gi[(size_t)NAG * 3 * CMM];
__device__ __align__(128) float g_gh[(size_t)NAG * 3 * CMM];
__device__ __align__(128) float g_v1[DAG * NH];
__device__ __align__(128) float g_v2[CMM * NH];
__device__ __align__(128) float g_w12[DGT * FSW];
__device__ unsigned g_gmx1[NH];
__device__ unsigned g_gmx2[NH];

__device__ int g_cnt_gt[NAG];
__device__ int g_cur_gt[NAG];
__device__ int g_offs_gt[NAG + 1];
__device__ int g_csr_gt[EGT];
__device__ int g_cnt_cm[NAG];
__device__ int g_cur_cm[NAG];
__device__ int g_offs_cm[NAG + 1];
__device__ int g_csr_cm[ECM];

__device__ __forceinline__ float lrelu(float x) { return x >= 0.f ? x : 0.2f * x; }
__device__ __forceinline__ unsigned fkey(float f) {
    unsigned u = __float_as_uint(f);
    return (u & 0x80000000u) ? ~u : (u | 0x80000000u);
}
__device__ __forceinline__ float fdecode(unsigned k) {
    return (k & 0x80000000u) ? __uint_as_float(k & 0x7fffffffu) : __uint_as_float(~k);
}

// ---------------- init ----------------
__global__ void init_kernel() {
    int t = blockIdx.x * blockDim.x + threadIdx.x;
    if (t < NAG) { g_cnt_gt[t] = 0; g_cur_gt[t] = 0; g_cnt_cm[t] = 0; g_cur_cm[t] = 0; }
    if (t < NH) { g_gmx1[t] = 0u; g_gmx2[t] = 0u; }
}

// ---------------- prep: W12 concat + folded a_r vectors ----------------
__global__ void prep_kernel(const float* __restrict__ w1_src, const float* __restrict__ w2_src,
                            const float* __restrict__ w1_dst, const float* __restrict__ a1_r,
                            const float* __restrict__ w2_dst, const float* __restrict__ a2_r) {
    int t = blockIdx.x * blockDim.x + threadIdx.x;
    if (t < DGT * FSW) {
        int k = t / FSW, c = t % FSW;
        g_w12[t] = (c < VIS) ? w1_src[k * VIS + c] : w2_src[k * CMM + (c - VIS)];
    } else if (t < DGT * FSW + 256) {
        int idx = t - DGT * FSW;
        int k = idx >> 2, h = idx & 3;
        float s = 0.f;
        #pragma unroll
        for (int d = 0; d < 16; d++) s += w1_dst[k * VIS + h * 16 + d] * a1_r[h * 16 + d];
        g_v1[idx] = s;
    } else if (t < DGT * FSW + 256 + 512) {
        int idx = t - DGT * FSW - 256;
        int k = idx >> 2, h = idx & 3;
        float s = 0.f;
        #pragma unroll
        for (int d = 0; d < 32; d++) s += w2_dst[k * CMM + h * 32 + d] * a2_r[h * 32 + d];
        g_v2[idx] = s;
    }
}

// ---------------- fused src projection + el epilogue ----------------
// C[NGT,192] = feat_gt @ W12 ; el1/el2 per-head dots computed in-epilogue.
__global__ void gemm_fs_k(const float* __restrict__ A, const float* __restrict__ a1l,
                          const float* __restrict__ a2l) {
    __shared__ float As[16][68];
    __shared__ float Bs[16][68];
    int tid = threadIdx.x;
    int tx = tid & 15, ty = tid >> 4;
    int row0 = blockIdx.x * 64;
    int col0 = blockIdx.y * 64;
    float acc[4][4] = {};
    int arow = tid >> 2, acol = (tid & 3) * 4;
    int brow = tid >> 4, bcol = (tid & 15) * 4;

    for (int k0 = 0; k0 < DGT; k0 += 16) {
        float4 av = make_float4(0.f, 0.f, 0.f, 0.f);
        int gr = row0 + arow;
        if (gr < NGT) av = *(const float4*)(A + (size_t)gr * DGT + k0 + acol);
        As[acol + 0][arow] = av.x; As[acol + 1][arow] = av.y;
        As[acol + 2][arow] = av.z; As[acol + 3][arow] = av.w;
        float4 bv = *(const float4*)(g_w12 + (size_t)(k0 + brow) * FSW + col0 + bcol);
        *(float4*)&Bs[brow][bcol] = bv;
        __syncthreads();
        #pragma unroll
        for (int k = 0; k < 16; k++) {
            float4 a = *(float4*)&As[k][ty * 4];
            float4 b = *(float4*)&Bs[k][tx * 4];
            acc[0][0] += a.x * b.x; acc[0][1] += a.x * b.y; acc[0][2] += a.x * b.z; acc[0][3] += a.x * b.w;
            acc[1][0] += a.y * b.x; acc[1][1] += a.y * b.y; acc[1][2] += a.y * b.z; acc[1][3] += a.y * b.w;
            acc[2][0] += a.z * b.x; acc[2][1] += a.z * b.y; acc[2][2] += a.z * b.z; acc[2][3] += a.z * b.w;
            acc[3][0] += a.w * b.x; acc[3][1] += a.w * b.y; acc[3][2] += a.w * b.z; acc[3][3] += a.w * b.w;
        }
        __syncthreads();
    }

    // write fs12 tile
    int c0 = col0 + tx * 4;
    #pragma unroll
    for (int i = 0; i < 4; i++) {
        int r = row0 + ty * 4 + i;
        if (r < NGT)
            *(float4*)(g_fs12 + (size_t)r * FSW + c0) =
                make_float4(acc[i][0], acc[i][1], acc[i][2], acc[i][3]);
    }

    // attention-dot epilogue: a-weights for this thread's 4 cols
    int y = blockIdx.y;
    float aw[4];
    if (y == 0) {
        #pragma unroll
        for (int j = 0; j < 4; j++) aw[j] = a1l[tx * 4 + j];         // flat [H*16]
    } else {
        int base = (y - 1) * 64 + tx * 4;
        #pragma unroll
        for (int j = 0; j < 4; j++) aw[j] = a2l[base + j];           // flat [H*32]
    }
    int gs = (y == 0) ? 4 : 8;   // threads per head group (16 or 32 cols)
    #pragma unroll
    for (int i = 0; i < 4; i++) {
        float p = acc[i][0] * aw[0] + acc[i][1] * aw[1] + acc[i][2] * aw[2] + acc[i][3] * aw[3];
        for (int off = gs >> 1; off >= 1; off >>= 1)
            p += __shfl_down_sync(0xffffffffu, p, off, gs);
        int r = row0 + ty * 4 + i;
        if ((tx & (gs - 1)) == 0 && r < NGT) {
            if (y == 0) g_el1[r * 4 + (tx >> 2)] = p;
            else        g_el2[r * 4 + (y - 1) * 2 + (tx >> 3)] = p;
        }
    }
}

// ---------------- global per-head max of el1/el2 ----------------
__global__ void gmax_kernel() {
    __shared__ unsigned s1[4], s2[4];
    int tid = threadIdx.x;
    if (tid < 4) { s1[tid] = 0u; s2[tid] = 0u; }
    __syncthreads();
    unsigned l1[4] = {0u, 0u, 0u, 0u}, l2[4] = {0u, 0u, 0u, 0u};
    for (int i = blockIdx.x * blockDim.x + tid; i < NGT; i += gridDim.x * blockDim.x) {
        float4 e1 = *(const float4*)&g_el1[i * 4];
        float4 e2 = *(const float4*)&g_el2[i * 4];
        l1[0] = max(l1[0], fkey(e1.x)); l1[1] = max(l1[1], fkey(e1.y));
        l1[2] = max(l1[2], fkey(e1.z)); l1[3] = max(l1[3], fkey(e1.w));
        l2[0] = max(l2[0], fkey(e2.x)); l2[1] = max(l2[1], fkey(e2.y));
        l2[2] = max(l2[2], fkey(e2.z)); l2[3] = max(l2[3], fkey(e2.w));
    }
    #pragma unroll
    for (int h = 0; h < 4; h++) { atomicMax(&s1[h], l1[h]); atomicMax(&s2[h], l2[h]); }
    __syncthreads();
    if (tid < 4) { atomicMax(&g_gmx1[tid], s1[tid]); atomicMax(&g_gmx2[tid], s2[tid]); }
}

// ---------------- generic tiled SGEMM (R3-proven shape) with ld params ----------------
#define FLAG_RELU 1
__global__ void gemm_k(const float* __restrict__ A, const float* __restrict__ B,
                       const float* __restrict__ bias, float* __restrict__ C,
                       int M, int K, int lda, int ldb, int ldc, int flags) {
    __shared__ float As[16][68];
    __shared__ float Bs[16][68];
    int tid = threadIdx.x;
    int tx = tid & 15, ty = tid >> 4;
    int row0 = blockIdx.x * 64;
    int col0 = blockIdx.y * 64;
    float acc[4][4] = {};
    int arow = tid >> 2, acol = (tid & 3) * 4;
    int brow = tid >> 4, bcol = (tid & 15) * 4;

    for (int k0 = 0; k0 < K; k0 += 16) {
        float4 av = make_float4(0.f, 0.f, 0.f, 0.f);
        int gr = row0 + arow;
        if (gr < M) av = *(const float4*)(A + (size_t)gr * lda + k0 + acol);
        As[acol + 0][arow] = av.x; As[acol + 1][arow] = av.y;
        As[acol + 2][arow] = av.z; As[acol + 3][arow] = av.w;
        float4 bv = *(const float4*)(B + (size_t)(k0 + brow) * ldb + col0 + bcol);
        *(float4*)&Bs[brow][bcol] = bv;
        __syncthreads();
        #pragma unroll
        for (int k = 0; k < 16; k++) {
            float4 a = *(float4*)&As[k][ty * 4];
            float4 b = *(float4*)&Bs[k][tx * 4];
            acc[0][0] += a.x * b.x; acc[0][1] += a.x * b.y; acc[0][2] += a.x * b.z; acc[0][3] += a.x * b.w;
            acc[1][0] += a.y * b.x; acc[1][1] += a.y * b.y; acc[1][2] += a.y * b.z; acc[1][3] += a.y * b.w;
            acc[2][0] += a.z * b.x; acc[2][1] += a.z * b.y; acc[2][2] += a.z * b.z; acc[2][3] += a.z * b.w;
            acc[3][0] += a.w * b.x; acc[3][1] += a.w * b.y; acc[3][2] += a.w * b.z; acc[3][3] += a.w * b.w;
        }
        __syncthreads();
    }
    int c0 = col0 + tx * 4;
    #pragma unroll
    for (int i = 0; i < 4; i++) {
        int r = row0 + ty * 4 + i;
        if (r < M) {
            float4 v = make_float4(acc[i][0], acc[i][1], acc[i][2], acc[i][3]);
            if (bias) {
                v.x += bias[c0]; v.y += bias[c0 + 1]; v.z += bias[c0 + 2]; v.w += bias[c0 + 3];
            }
            if (flags & FLAG_RELU) {
                v.x = fmaxf(v.x, 0.f); v.y = fmaxf(v.y, 0.f);
                v.z = fmaxf(v.z, 0.f); v.w = fmaxf(v.w, 0.f);
            }
            *(float4*)(C + (size_t)r * ldc + c0) = v;
        }
    }
}

// ---------------- er1 = feat_agent @ v1 ----------------
__global__ void er1_kernel(const float* __restrict__ feat_agent) {
    int t = blockIdx.x * blockDim.x + threadIdx.x;
    if (t >= NAG * NH) return;
    int n = t >> 2, h = t & 3;
    const float* f = feat_agent + (size_t)n * DAG;
    float s = 0.f;
    #pragma unroll 8
    for (int k = 0; k < DAG; k++) s += f[k] * g_v1[k * NH + h];
    g_er1[t] = s;
}

// ---------------- CSR build (merged) ----------------
__global__ void count2_kernel(const int* __restrict__ gt_dst, const int* __restrict__ cm_dst) {
    int e = blockIdx.x * blockDim.x + threadIdx.x;
    if (e < EGT) atomicAdd(&g_cnt_gt[gt_dst[e]], 1);
    else if (e < EGT + ECM) atomicAdd(&g_cnt_cm[cm_dst[e - EGT]], 1);
}

__device__ void scan_body(const int* __restrict__ cnt, int* __restrict__ offs, int n) {
    __shared__ int wsum[32];
    __shared__ int carry;
    int tid = threadIdx.x, lane = tid & 31, wid = tid >> 5;
    if (tid == 0) carry = 0;
    __syncthreads();
    for (int base = 0; base < n; base += 1024) {
        int i = base + tid;
        int v = (i < n) ? cnt[i] : 0;
        int x = v;
        #pragma unroll
        for (int off = 1; off < 32; off <<= 1) {
            int t = __shfl_up_sync(0xffffffffu, x, off);
            if (lane >= off) x += t;
        }
        if (lane == 31) wsum[wid] = x;
        __syncthreads();
        if (wid == 0) {
            int s = wsum[lane];
            #pragma unroll
            for (int off = 1; off < 32; off <<= 1) {
                int t = __shfl_up_sync(0xffffffffu, s, off);
                if (lane >= off) s += t;
            }
            wsum[lane] = s;
        }
        __syncthreads();
        int wpre = (wid > 0) ? wsum[wid - 1] : 0;
        int incl = carry + wpre + x;
        if (i < n) offs[i] = incl - v;
        __syncthreads();
        if (tid == 1023) carry = incl;
        __syncthreads();
    }
    if (tid == 0) offs[n] = carry;
}

__global__ void scan2_kernel() {
    if (blockIdx.x == 0) scan_body(g_cnt_gt, g_offs_gt, NAG);
    else                 scan_body(g_cnt_cm, g_offs_cm, NAG);
}

__global__ void scatter2_kernel(const int* __restrict__ gt_src, const int* __restrict__ gt_dst,
                                const int* __restrict__ cm_src, const int* __restrict__ cm_dst) {
    int e = blockIdx.x * blockDim.x + threadIdx.x;
    if (e < EGT) {
        int d = gt_dst[e];
        int p = atomicAdd(&g_cur_gt[d], 1);
        g_csr_gt[g_offs_gt[d] + p] = gt_src[e];
    } else if (e < EGT + ECM) {
        int e2 = e - EGT;
        int d = cm_dst[e2];
        int p = atomicAdd(&g_cur_cm[d], 1);
        g_csr_cm[g_offs_cm[d] + p] = cm_src[e2];
    }
}

// ---------------- GAT1: single-pass softmax (global shift) + er2 epilogue ----------------
__global__ void gat1_kernel(const float* __restrict__ feat_agent, const float* __restrict__ b1) {
    int w = (blockIdx.x * blockDim.x + threadIdx.x) >> 5;
    if (w >= NAG) return;
    int lane = threadIdx.x & 31;
    int beg = g_offs_gt[w], end = g_offs_gt[w + 1];
    float4 er = *(const float4*)&g_er1[w * 4];
    float m0 = fmaxf(fdecode(g_gmx1[0]) + er.x, 0.f);
    float m1 = fmaxf(fdecode(g_gmx1[1]) + er.y, 0.f);
    float m2 = fmaxf(fdecode(g_gmx1[2]) + er.z, 0.f);
    float m3 = fmaxf(fdecode(g_gmx1[3]) + er.w, 0.f);
    float d0 = 0.f, d1 = 0.f, d2 = 0.f, d3 = 0.f;
    float acc0 = 0.f, acc1 = 0.f;
    int hs = lane >> 4;
    #pragma unroll 2
    for (int e = beg; e < end; e++) {
        int s = g_csr_gt[e];
        float4 el = *(const float4*)&g_el1[s * 4];
        float p0 = __expf(lrelu(el.x + er.x) - m0);
        float p1 = __expf(lrelu(el.y + er.y) - m1);
        float p2 = __expf(lrelu(el.z + er.z) - m2);
        float p3 = __expf(lrelu(el.w + er.w) - m3);
        d0 += p0; d1 += p1; d2 += p2; d3 += p3;
        float pa = (hs == 0) ? p0 : p1;
        float pb = (hs == 0) ? p2 : p3;
        const float* fr = g_fs12 + (size_t)s * FSW;
        acc0 += pa * fr[lane];
        acc1 += pb * fr[32 + lane];
    }
    float da = (hs == 0) ? d0 : d1;
    float db = (hs == 0) ? d2 : d3;
    float ia = da > 0.f ? 1.f / da : 0.f;
    float ib = db > 0.f ? 1.f / db : 0.f;
    float fa0 = feat_agent[(size_t)w * DAG + lane];
    float fa1 = feat_agent[(size_t)w * DAG + 32 + lane];
    float o0 = fmaxf(acc0 * ia + fa0 + b1[lane], 0.f);
    float o1 = fmaxf(acc1 * ib + fa1 + b1[32 + lane], 0.f);
    float* dr = g_dst2 + (size_t)w * CMM;
    dr[lane] = o0; dr[32 + lane] = o1;
    dr[64 + lane] = fa0; dr[96 + lane] = fa1;

    // er2 = dst2_row . v2[:,h] (warp butterfly reduce)
    float4 va = *(const float4*)&g_v2[lane * 4];
    float4 vb = *(const float4*)&g_v2[(32 + lane) * 4];
    float4 vc = *(const float4*)&g_v2[(64 + lane) * 4];
    float4 vd = *(const float4*)&g_v2[(96 + lane) * 4];
    float4 e2;
    e2.x = o0 * va.x + o1 * vb.x + fa0 * vc.x + fa1 * vd.x;
    e2.y = o0 * va.y + o1 * vb.y + fa0 * vc.y + fa1 * vd.y;
    e2.z = o0 * va.z + o1 * vb.z + fa0 * vc.z + fa1 * vd.z;
    e2.w = o0 * va.w + o1 * vb.w + fa0 * vc.w + fa1 * vd.w;
    #pragma unroll
    for (int off = 16; off >= 1; off >>= 1) {
        e2.x += __shfl_xor_sync(0xffffffffu, e2.x, off);
        e2.y += __shfl_xor_sync(0xffffffffu, e2.y, off);
        e2.z += __shfl_xor_sync(0xffffffffu, e2.z, off);
        e2.w += __shfl_xor_sync(0xffffffffu, e2.w, off);
    }
    if (lane == 0) *(float4*)&g_er2[w * 4] = e2;
}

// ---------------- GAT2: single-pass; writes h into g_hy (stride 192) ----------------
__global__ void gat2_kernel(const float* __restrict__ b2) {
    int w = (blockIdx.x * blockDim.x + threadIdx.x) >> 5;
    if (w >= NAG) return;
    int lane = threadIdx.x & 31;
    int beg = g_offs_gt[w], end = g_offs_gt[w + 1];
    float4 er = *(const float4*)&g_er2[w * 4];
    float m0 = fmaxf(fdecode(g_gmx2[0]) + er.x, 0.f);
    float m1 = fmaxf(fdecode(g_gmx2[1]) + er.y, 0.f);
    float m2 = fmaxf(fdecode(g_gmx2[2]) + er.z, 0.f);
    float m3 = fmaxf(fdecode(g_gmx2[3]) + er.w, 0.f);
    float d0 = 0.f, d1 = 0.f, d2 = 0.f, d3 = 0.f;
    float a0 = 0.f, a1 = 0.f, a2 = 0.f, a3 = 0.f;
    #pragma unroll 2
    for (int e = beg; e < end; e++) {
        int s = g_csr_gt[e];
        float4 el = *(const float4*)&g_el2[s * 4];
        float p0 = __expf(lrelu(el.x + er.x) - m0);
        float p1 = __expf(lrelu(el.y + er.y) - m1);
        float p2 = __expf(lrelu(el.z + er.z) - m2);
        float p3 = __expf(lrelu(el.w + er.w) - m3);
        d0 += p0; d1 += p1; d2 += p2; d3 += p3;
        const float* fr = g_fs12 + (size_t)s * FSW + VIS;
        a0 += p0 * fr[lane];
        a1 += p1 * fr[32 + lane];
        a2 += p2 * fr[64 + lane];
        a3 += p3 * fr[96 + lane];
    }
    float i0 = d0 > 0.f ? 1.f / d0 : 0.f;
    float i1 = d1 > 0.f ? 1.f / d1 : 0.f;
    float i2 = d2 > 0.f ? 1.f / d2 : 0.f;
    float i3 = d3 > 0.f ? 1.f / d3 : 0.f;
    const float* dr = g_dst2 + (size_t)w * CMM;
    float* hr = g_hy + (size_t)w * HYW;
    hr[lane]      = fmaxf(a0 * i0 + dr[lane]      + b2[lane],      0.f);
    hr[32 + lane] = fmaxf(a1 * i1 + dr[32 + lane] + b2[32 + lane], 0.f);
    hr[64 + lane] = fmaxf(a2 * i2 + dr[64 + lane] + b2[64 + lane], 0.f);
    hr[96 + lane] = fmaxf(a3 * i3 + dr[96 + lane] + b2[96 + lane], 0.f);
}

// ---------------- comm mailbox mean -> y part of g_hy ----------------
__global__ void comm_agg_kernel() {
    int w = (blockIdx.x * blockDim.x + threadIdx.x) >> 5;
    if (w >= NAG) return;
    int lane = threadIdx.x & 31;
    int beg = g_offs_cm[w], end = g_offs_cm[w + 1];
    float a0 = 0.f, a1 = 0.f;
    #pragma unroll 2
    for (int e = beg; e < end; e++) {
        int s = g_csr_cm[e];
        const float* mr = g_m + (size_t)s * MSG;
        a0 += mr[lane];
        a1 += mr[32 + lane];
    }
    int deg = end - beg;
    float inv = 1.f / (float)(deg > 0 ? deg : 1);
    g_hy[(size_t)w * HYW + CMM + lane] = a0 * inv;
    g_hy[(size_t)w * HYW + CMM + 32 + lane] = a1 * inv;
}

// ---------------- GRU elementwise combine -> h part of g_hy ----------------
__global__ void gru_kernel(const float* __restrict__ zz, int zlda) {
    int idx = blockIdx.x * blockDim.x + threadIdx.x;
    if (idx >= NAG * CMM) return;
    int n = idx >> 7, j = idx & 127;
    size_t base = (size_t)n * 384;
    float ir = g_gi[base + j],        hr = g_gh[base + j];
    float iz = g_gi[base + 128 + j],  hz = g_gh[base + 128 + j];
    float in_ = g_gi[base + 256 + j], hn = g_gh[base + 256 + j];
    float r  = 1.f / (1.f + __expf(-(ir + hr)));
    float zg = 1.f / (1.f + __expf(-(iz + hz)));
    float nn = tanhf(in_ + r * hn);
    float zv = zz[(size_t)n * zlda + j];
    g_hy[(size_t)n * HYW + j] = (1.f - zg) * nn + zg * zv;
}

// ---------------- output head + zz copy ----------------
__global__ void out_kernel(const float* __restrict__ W, const float* __restrict__ b,
                           float* __restrict__ out) {
    int idx = blockIdx.x * blockDim.x + threadIdx.x;
    if (idx >= NAG * OUTD) return;
    int n = idx / OUTD, j = idx % OUTD;
    const float* hr = g_hy + (size_t)n * HYW;
    float s = b[j];
    #pragma unroll 8
    for (int k = 0; k < CMM; k++) s += hr[k] * W[k * OUTD + j];
    out[idx] = s;
}

__global__ void zcopy_kernel(float* __restrict__ out) {
    int idx = blockIdx.x * blockDim.x + threadIdx.x;
    if (idx >= NAG * CMM) return;
    out[idx] = g_hy[(size_t)(idx >> 7) * HYW + (idx & 127)];
}

// ---------------- host launch ----------------
static void gemm(const float* A, const float* B, const float* bias, float* C,
                 int M, int N, int K, int lda, int ldb, int ldc, int flags) {
    dim3 grid((M + 63) / 64, N / 64);
    gemm_k<<<grid, 256>>>(A, B, bias, C, M, K, lda, ldb, ldc, flags);
}

extern "C" void kernel_launch(void* const* d_in, const int* in_sizes, int n_in,
                              void* d_out, int out_size) {
    const float* feat_gt    = (const float*)d_in[0];
    const float* feat_agent = (const float*)d_in[1];
    const float* z          = (const float*)d_in[2];
    const int*   gt_src     = (const int*)d_in[3];
    const int*   gt_dst     = (const int*)d_in[4];
    const int*   comm_src   = (const int*)d_in[5];
    const int*   comm_dst   = (const int*)d_in[6];
    const float* w1_src     = (const float*)d_in[7];
    const float* w1_dst     = (const float*)d_in[8];
    const float* a1_l       = (const float*)d_in[9];
    const float* a1_r       = (const float*)d_in[10];
    const float* b1         = (const float*)d_in[11];
    const float* w2_src     = (const float*)d_in[12];
    const float* w2_dst     = (const float*)d_in[13];
    const float* a2_l       = (const float*)d_in[14];
    const float* a2_r       = (const float*)d_in[15];
    const float* b2         = (const float*)d_in[16];
    const float* enc_w1     = (const float*)d_in[17];
    const float* enc_b1     = (const float*)d_in[18];
    const float* enc_w2     = (const float*)d_in[19];
    const float* enc_b2     = (const float*)d_in[20];
    const float* gw_ih      = (const float*)d_in[21];
    const float* gw_hh      = (const float*)d_in[22];
    const float* gb_ih      = (const float*)d_in[23];
    const float* gb_hh      = (const float*)d_in[24];
    const float* out_w      = (const float*)d_in[25];
    const float* out_b      = (const float*)d_in[26];

    float *p_hy, *p_t, *p_m, *p_gi, *p_gh;
    cudaGetSymbolAddress((void**)&p_hy, g_hy);
    cudaGetSymbolAddress((void**)&p_t,  g_t128);
    cudaGetSymbolAddress((void**)&p_m,  g_m);
    cudaGetSymbolAddress((void**)&p_gi, g_gi);
    cudaGetSymbolAddress((void**)&p_gh, g_gh);

    // 1) init + weight prep
    init_kernel<<<(NAG + 255) / 256, 256>>>();
    prep_kernel<<<(DGT * FSW + 768 + 255) / 256, 256>>>(w1_src, w2_src, w1_dst, a1_r, w2_dst, a2_r);

    // 2) fused src projections + el epilogue, then global max + er1
    {
        dim3 grid((NGT + 63) / 64, FSW / 64);
        gemm_fs_k<<<grid, 256>>>(feat_gt, a1_l, a2_l);
    }
    gmax_kernel<<<296, 256>>>();
    er1_kernel<<<(NAG * NH + 255) / 256, 256>>>(feat_agent);

    // 3) CSR build for both edge lists (merged launches)
    count2_kernel<<<(EGT + ECM + 255) / 256, 256>>>(gt_dst, comm_dst);
    scan2_kernel<<<2, 1024>>>();
    scatter2_kernel<<<(EGT + ECM + 255) / 256, 256>>>(gt_src, gt_dst, comm_src, comm_dst);

    // 4) GAT stage 1 (-> dst2, er2), stage 2 (-> h in g_hy)
    gat1_kernel<<<(NAG * 32 + 255) / 256, 256>>>(feat_agent, b1);
    gat2_kernel<<<(NAG * 32 + 255) / 256, 256>>>(b2);

    // 5) two comm steps
    const float* zz = z; int zlda = CMM;
    for (int step = 0; step < 2; step++) {
        gemm(p_hy, enc_w1, enc_b1, p_t, NAG, 128, CMM, HYW, 128, 128, FLAG_RELU);
        gemm(p_t, enc_w2, enc_b2, p_m, NAG, MSG, 128, 128, MSG, MSG, FLAG_RELU);
        comm_agg_kernel<<<(NAG * 32 + 255) / 256, 256>>>();
        // gi = [h|y] @ W_ih in one K=192 GEMM
        gemm(p_hy, gw_ih, gb_ih, p_gi, NAG, 384, HYW, HYW, 384, 384, 0);
        gemm(zz, gw_hh, gb_hh, p_gh, NAG, 384, CMM, zlda, 384, 384, 0);
        gru_kernel<<<(NAG * CMM + 255) / 256, 256>>>(zz, zlda);
        zz = p_hy; zlda = HYW;   // after update, zz == h (cols 0..127 of g_hy)
    }

    // 6) outputs: (h_out [NAG,5], zz [NAG,128])
    float* out = (float*)d_out;
    if (out_size == NAG * CMM) {
        zcopy_kernel<<<(NAG * CMM + 255) / 256, 256>>>(out);
    } else if (out_size == NAG * OUTD) {
        out_kernel<<<(NAG * OUTD + 255) / 256, 256>>>(out_w, out_b, out);
    } else {
        out_kernel<<<(NAG * OUTD + 255) / 256, 256>>>(out_w, out_b, out);
        zcopy_kernel<<<(NAG * CMM + 255) / 256, 256>>>(out + NAG * OUTD);
    }
}

// round 9
// speedup vs baseline: 1.5666x; 1.5666x over previous
#include <cuda_runtime.h>
#include <math.h>

// ---------------- problem constants ----------------
#define NGT   100000
#define NAG   20000
#define EGT   640000
#define ECM   320000
#define DGT   32
#define DAG   64
#define VIS   64
#define CMM   128
#define MSG   64
#define OUTD  5
#define NH    4

// ---------------- scratch (device globals; no cudaMalloc allowed) ----------------
__device__ __align__(128) float g_fs1[NGT * VIS];
__device__ __align__(128) float g_el1[NGT * NH];
__device__ __align__(128) float g_fs2[NGT * CMM];
__device__ __align__(128) float g_el2[NGT * NH];
__device__ __align__(128) float g_er1[NAG * NH];
__device__ __align__(128) float g_er2[NAG * NH];
__device__ __align__(128) float g_dst2[NAG * CMM];   // [h_vis1 | feat_agent]
__device__ __align__(128) float g_h[NAG * CMM];
__device__ __align__(128) float g_t128[NAG * CMM];
__device__ __align__(128) float g_m[NAG * MSG];
__device__ __align__(128) float g_y[NAG * MSG];
__device__ __align__(128) float g_gi[NAG * 3 * CMM];
__device__ __align__(128) float g_gh[NAG * 3 * CMM];
__device__ __align__(128) float g_v1[DAG * NH];
__device__ __align__(128) float g_v2[CMM * NH];
__device__ unsigned g_gmx1[NH];
__device__ unsigned g_gmx2[NH];

__device__ int g_cnt_gt[NAG];
__device__ int g_cur_gt[NAG];
__device__ int g_offs_gt[NAG + 1];
__device__ int g_csr_gt[EGT];
__device__ int g_cnt_cm[NAG];
__device__ int g_cur_cm[NAG];
__device__ int g_offs_cm[NAG + 1];
__device__ int g_csr_cm[ECM];

__device__ __forceinline__ float lrelu(float x) { return x >= 0.f ? x : 0.2f * x; }
__device__ __forceinline__ unsigned fkey(float f) {
    unsigned u = __float_as_uint(f);
    return (u & 0x80000000u) ? ~u : (u | 0x80000000u);
}
__device__ __forceinline__ float fdecode(unsigned k) {
    return (k & 0x80000000u) ? __uint_as_float(k & 0x7fffffffu) : __uint_as_float(~k);
}

// ---------------- init: zero counters ----------------
__global__ void init_kernel() {
    int t = blockIdx.x * blockDim.x + threadIdx.x;
    if (t < NAG) { g_cnt_gt[t] = 0; g_cur_gt[t] = 0; g_cnt_cm[t] = 0; g_cur_cm[t] = 0; }
    if (t < NH) { g_gmx1[t] = 0u; g_gmx2[t] = 0u; }
}

// ---------------- fold W_dst @ a_r into v[k][h] ----------------
__global__ void v12_kernel(const float* __restrict__ w1_dst, const float* __restrict__ a1_r,
                           const float* __restrict__ w2_dst, const float* __restrict__ a2_r) {
    int t = threadIdx.x;           // 256 threads, one block
    {   // v1: [64][4], dh=16
        int k = t >> 2, h = t & 3;
        float s = 0.f;
        #pragma unroll
        for (int d = 0; d < 16; d++) s += w1_dst[k * VIS + h * 16 + d] * a1_r[h * 16 + d];
        g_v1[t] = s;
    }
    #pragma unroll
    for (int i = 0; i < 2; i++) {  // v2: [128][4], dh=32
        int idx = t + i * 256;
        int k = idx >> 2, h = idx & 3;
        float s = 0.f;
        #pragma unroll
        for (int d = 0; d < 32; d++) s += w2_dst[k * CMM + h * 32 + d] * a2_r[h * 32 + d];
        g_v2[idx] = s;
    }
}

// ---------------- generic tiled SGEMM: C = act(A[M,K] x B[K,N](ldb) + bias [+ C]) ----------------
#define FLAG_RELU 1
#define FLAG_ACC  2
__global__ void gemm_k(const float* __restrict__ A, const float* __restrict__ B,
                       const float* __restrict__ bias, float* __restrict__ C,
                       int M, int N, int K, int ldb, int flags) {
    __shared__ float As[16][68];
    __shared__ float Bs[16][68];
    int tid = threadIdx.x;
    int row0 = blockIdx.x * 64;
    int col0 = blockIdx.y * 64;
    int ty = tid >> 4, tx = tid & 15;
    float acc[4][4] = {};
    int arow = tid >> 2;            // 0..63
    int acol = (tid & 3) * 4;       // 0,4,8,12
    int brow = tid >> 4;            // 0..15
    int bcol = (tid & 15) * 4;      // 0..60

    for (int k0 = 0; k0 < K; k0 += 16) {
        float4 av = make_float4(0.f, 0.f, 0.f, 0.f);
        int gr = row0 + arow;
        if (gr < M) av = *(const float4*)(A + (size_t)gr * K + k0 + acol);
        As[acol + 0][arow] = av.x; As[acol + 1][arow] = av.y;
        As[acol + 2][arow] = av.z; As[acol + 3][arow] = av.w;
        float4 bv = *(const float4*)(B + (size_t)(k0 + brow) * ldb + col0 + bcol);
        *(float4*)&Bs[brow][bcol] = bv;
        __syncthreads();
        #pragma unroll
        for (int k = 0; k < 16; k++) {
            float4 a = *(float4*)&As[k][ty * 4];
            float4 b = *(float4*)&Bs[k][tx * 4];
            acc[0][0] += a.x * b.x; acc[0][1] += a.x * b.y; acc[0][2] += a.x * b.z; acc[0][3] += a.x * b.w;
            acc[1][0] += a.y * b.x; acc[1][1] += a.y * b.y; acc[1][2] += a.y * b.z; acc[1][3] += a.y * b.w;
            acc[2][0] += a.z * b.x; acc[2][1] += a.z * b.y; acc[2][2] += a.z * b.z; acc[2][3] += a.z * b.w;
            acc[3][0] += a.w * b.x; acc[3][1] += a.w * b.y; acc[3][2] += a.w * b.z; acc[3][3] += a.w * b.w;
        }
        __syncthreads();
    }
    int c0 = col0 + tx * 4;
    #pragma unroll
    for (int i = 0; i < 4; i++) {
        int r = row0 + ty * 4 + i;
        if (r < M) {
            float4 v = make_float4(acc[i][0], acc[i][1], acc[i][2], acc[i][3]);
            float* cp = C + (size_t)r * N + c0;
            if (flags & FLAG_ACC) {
                float4 o = *(float4*)cp;
                v.x += o.x; v.y += o.y; v.z += o.z; v.w += o.w;
            }
            if (bias) {
                v.x += bias[c0]; v.y += bias[c0 + 1]; v.z += bias[c0 + 2]; v.w += bias[c0 + 3];
            }
            if (flags & FLAG_RELU) {
                v.x = fmaxf(v.x, 0.f); v.y = fmaxf(v.y, 0.f); v.z = fmaxf(v.z, 0.f); v.w = fmaxf(v.w, 0.f);
            }
            *(float4*)cp = v;
        }
    }
}

// ---------------- el = sum over dh of fs * a_l ----------------
__global__ void el_kernel(const float* __restrict__ a1l, const float* __restrict__ a2l) {
    int t = blockIdx.x * blockDim.x + threadIdx.x;
    if (t < NGT * NH) {
        int i = t >> 2, h = t & 3;
        const float* f = g_fs1 + (size_t)i * VIS + h * 16;
        const float* a = a1l + h * 16;
        float s = 0.f;
        #pragma unroll
        for (int d = 0; d < 16; d++) s += f[d] * a[d];
        g_el1[t] = s;
    } else if (t < 2 * NGT * NH) {
        int u = t - NGT * NH;
        int i = u >> 2, h = u & 3;
        const float* f = g_fs2 + (size_t)i * CMM + h * 32;
        const float* a = a2l + h * 32;
        float s = 0.f;
        #pragma unroll
        for (int d = 0; d < 32; d++) s += f[d] * a[d];
        g_el2[u] = s;
    }
}

// ---------------- global per-head max of el1/el2 ----------------
__global__ void gmax_kernel() {
    __shared__ unsigned s1[4], s2[4];
    int tid = threadIdx.x;
    if (tid < 4) { s1[tid] = 0u; s2[tid] = 0u; }
    __syncthreads();
    unsigned l1[4] = {0u, 0u, 0u, 0u}, l2[4] = {0u, 0u, 0u, 0u};
    for (int i = blockIdx.x * blockDim.x + tid; i < NGT; i += gridDim.x * blockDim.x) {
        float4 e1 = *(const float4*)&g_el1[i * 4];
        float4 e2 = *(const float4*)&g_el2[i * 4];
        l1[0] = max(l1[0], fkey(e1.x)); l1[1] = max(l1[1], fkey(e1.y));
        l1[2] = max(l1[2], fkey(e1.z)); l1[3] = max(l1[3], fkey(e1.w));
        l2[0] = max(l2[0], fkey(e2.x)); l2[1] = max(l2[1], fkey(e2.y));
        l2[2] = max(l2[2], fkey(e2.z)); l2[3] = max(l2[3], fkey(e2.w));
    }
    #pragma unroll
    for (int h = 0; h < 4; h++) { atomicMax(&s1[h], l1[h]); atomicMax(&s2[h], l2[h]); }
    __syncthreads();
    if (tid < 4) { atomicMax(&g_gmx1[tid], s1[tid]); atomicMax(&g_gmx2[tid], s2[tid]); }
}

// ---------------- er1 = feat_agent @ v1 ----------------
__global__ void er1_kernel(const float* __restrict__ feat_agent) {
    int t = blockIdx.x * blockDim.x + threadIdx.x;
    if (t >= NAG * NH) return;
    int n = t >> 2, h = t & 3;
    const float* f = feat_agent + (size_t)n * DAG;
    float s = 0.f;
    #pragma unroll 8
    for (int k = 0; k < DAG; k++) s += f[k] * g_v1[k * NH + h];
    g_er1[t] = s;
}

// ---------------- er2 = dst2 @ v2 ----------------
__global__ void er2_kernel() {
    int t = blockIdx.x * blockDim.x + threadIdx.x;
    if (t >= NAG * NH) return;
    int n = t >> 2, h = t & 3;
    const float* f = g_dst2 + (size_t)n * CMM;
    float s = 0.f;
    #pragma unroll 8
    for (int k = 0; k < CMM; k++) s += f[k] * g_v2[k * NH + h];
    g_er2[t] = s;
}

// ---------------- CSR build (merged launches) ----------------
__global__ void count2_kernel(const int* __restrict__ gt_dst, const int* __restrict__ cm_dst) {
    int e = blockIdx.x * blockDim.x + threadIdx.x;
    if (e < EGT) atomicAdd(&g_cnt_gt[gt_dst[e]], 1);
    else if (e < EGT + ECM) atomicAdd(&g_cnt_cm[cm_dst[e - EGT]], 1);
}

__device__ void scan_body(const int* __restrict__ cnt, int* __restrict__ offs, int n) {
    __shared__ int wsum[32];
    __shared__ int carry;
    int tid = threadIdx.x, lane = tid & 31, wid = tid >> 5;
    if (tid == 0) carry = 0;
    __syncthreads();
    for (int base = 0; base < n; base += 1024) {
        int i = base + tid;
        int v = (i < n) ? cnt[i] : 0;
        int x = v;
        #pragma unroll
        for (int off = 1; off < 32; off <<= 1) {
            int t = __shfl_up_sync(0xffffffffu, x, off);
            if (lane >= off) x += t;
        }
        if (lane == 31) wsum[wid] = x;
        __syncthreads();
        if (wid == 0) {
            int s = wsum[lane];
            #pragma unroll
            for (int off = 1; off < 32; off <<= 1) {
                int t = __shfl_up_sync(0xffffffffu, s, off);
                if (lane >= off) s += t;
            }
            wsum[lane] = s;
        }
        __syncthreads();
        int wpre = (wid > 0) ? wsum[wid - 1] : 0;
        int incl = carry + wpre + x;
        if (i < n) offs[i] = incl - v;
        __syncthreads();
        if (tid == 1023) carry = incl;
        __syncthreads();
    }
    if (tid == 0) offs[n] = carry;
}

__global__ void scan2_kernel() {
    if (blockIdx.x == 0) scan_body(g_cnt_gt, g_offs_gt, NAG);
    else                 scan_body(g_cnt_cm, g_offs_cm, NAG);
}

__global__ void scatter2_kernel(const int* __restrict__ gt_src, const int* __restrict__ gt_dst,
                                const int* __restrict__ cm_src, const int* __restrict__ cm_dst) {
    int e = blockIdx.x * blockDim.x + threadIdx.x;
    if (e < EGT) {
        int d = gt_dst[e];
        int p = atomicAdd(&g_cur_gt[d], 1);
        g_csr_gt[g_offs_gt[d] + p] = gt_src[e];
    } else if (e < EGT + ECM) {
        int e2 = e - EGT;
        int d = cm_dst[e2];
        int p = atomicAdd(&g_cur_cm[d], 1);
        g_csr_cm[g_offs_cm[d] + p] = cm_src[e2];
    }
}

// ---------------- GAT1: single-pass softmax via global shift (warp per dst) ----------------
__global__ void gat1_kernel(const float* __restrict__ feat_agent, const float* __restrict__ b1) {
    int w = (blockIdx.x * blockDim.x + threadIdx.x) >> 5;
    if (w >= NAG) return;
    int lane = threadIdx.x & 31;
    int beg = g_offs_gt[w], end = g_offs_gt[w + 1];
    float4 er = *(const float4*)&g_er1[w * 4];
    // m_h = lrelu(global_max(el_h) + er_h) >= every lrelu(el_s + er_h) (monotone); softmax shift-invariant.
    float m0 = lrelu(fdecode(g_gmx1[0]) + er.x);
    float m1 = lrelu(fdecode(g_gmx1[1]) + er.y);
    float m2 = lrelu(fdecode(g_gmx1[2]) + er.z);
    float m3 = lrelu(fdecode(g_gmx1[3]) + er.w);
    float d0 = 0.f, d1 = 0.f, d2 = 0.f, d3 = 0.f;
    float acc0 = 0.f, acc1 = 0.f;
    int hs = lane >> 4;  // col lane -> head hs (0/1); col 32+lane -> head 2+hs
    for (int e = beg; e < end; e++) {
        int s = g_csr_gt[e];
        float4 el = *(const float4*)&g_el1[s * 4];
        float p0 = __expf(lrelu(el.x + er.x) - m0);
        float p1 = __expf(lrelu(el.y + er.y) - m1);
        float p2 = __expf(lrelu(el.z + er.z) - m2);
        float p3 = __expf(lrelu(el.w + er.w) - m3);
        d0 += p0; d1 += p1; d2 += p2; d3 += p3;
        float pa = (hs == 0) ? p0 : p1;
        float pb = (hs == 0) ? p2 : p3;
        const float* fr = g_fs1 + (size_t)s * VIS;
        acc0 += pa * fr[lane];
        acc1 += pb * fr[32 + lane];
    }
    float da = (hs == 0) ? d0 : d1;
    float db = (hs == 0) ? d2 : d3;
    float ia = da > 0.f ? 1.f / da : 0.f;
    float ib = db > 0.f ? 1.f / db : 0.f;
    float fa0 = feat_agent[(size_t)w * DAG + lane];
    float fa1 = feat_agent[(size_t)w * DAG + 32 + lane];
    float o0 = fmaxf(acc0 * ia + fa0 + b1[lane], 0.f);
    float o1 = fmaxf(acc1 * ib + fa1 + b1[32 + lane], 0.f);
    float* dr = g_dst2 + (size_t)w * CMM;
    dr[lane] = o0; dr[32 + lane] = o1;
    dr[64 + lane] = fa0; dr[96 + lane] = fa1;    // concat feat_agent
}

// ---------------- GAT2: single-pass softmax via global shift ----------------
__global__ void gat2_kernel(const float* __restrict__ b2) {
    int w = (blockIdx.x * blockDim.x + threadIdx.x) >> 5;
    if (w >= NAG) return;
    int lane = threadIdx.x & 31;
    int beg = g_offs_gt[w], end = g_offs_gt[w + 1];
    float4 er = *(const float4*)&g_er2[w * 4];
    float m0 = lrelu(fdecode(g_gmx2[0]) + er.x);
    float m1 = lrelu(fdecode(g_gmx2[1]) + er.y);
    float m2 = lrelu(fdecode(g_gmx2[2]) + er.z);
    float m3 = lrelu(fdecode(g_gmx2[3]) + er.w);
    float d0 = 0.f, d1 = 0.f, d2 = 0.f, d3 = 0.f;
    float a0 = 0.f, a1 = 0.f, a2 = 0.f, a3 = 0.f;
    for (int e = beg; e < end; e++) {
        int s = g_csr_gt[e];
        float4 el = *(const float4*)&g_el2[s * 4];
        float p0 = __expf(lrelu(el.x + er.x) - m0);
        float p1 = __expf(lrelu(el.y + er.y) - m1);
        float p2 = __expf(lrelu(el.z + er.z) - m2);
        float p3 = __expf(lrelu(el.w + er.w) - m3);
        d0 += p0; d1 += p1; d2 += p2; d3 += p3;
        const float* fr = g_fs2 + (size_t)s * CMM;
        a0 += p0 * fr[lane];
        a1 += p1 * fr[32 + lane];
        a2 += p2 * fr[64 + lane];
        a3 += p3 * fr[96 + lane];
    }
    float i0 = d0 > 0.f ? 1.f / d0 : 0.f;
    float i1 = d1 > 0.f ? 1.f / d1 : 0.f;
    float i2 = d2 > 0.f ? 1.f / d2 : 0.f;
    float i3 = d3 > 0.f ? 1.f / d3 : 0.f;
    const float* dr = g_dst2 + (size_t)w * CMM;
    float* hr = g_h + (size_t)w * CMM;
    hr[lane]      = fmaxf(a0 * i0 + dr[lane]      + b2[lane],      0.f);
    hr[32 + lane] = fmaxf(a1 * i1 + dr[32 + lane] + b2[32 + lane], 0.f);
    hr[64 + lane] = fmaxf(a2 * i2 + dr[64 + lane] + b2[64 + lane], 0.f);
    hr[96 + lane] = fmaxf(a3 * i3 + dr[96 + lane] + b2[96 + lane], 0.f);
}

// ---------------- comm mailbox mean ----------------
__global__ void comm_agg_kernel() {
    int w = (blockIdx.x * blockDim.x + threadIdx.x) >> 5;
    if (w >= NAG) return;
    int lane = threadIdx.x & 31;
    int beg = g_offs_cm[w], end = g_offs_cm[w + 1];
    float a0 = 0.f, a1 = 0.f;
    for (int e = beg; e < end; e++) {
        int s = g_csr_cm[e];
        const float* mr = g_m + (size_t)s * MSG;
        a0 += mr[lane];
        a1 += mr[32 + lane];
    }
    int deg = end - beg;
    float inv = 1.f / (float)(deg > 0 ? deg : 1);
    g_y[(size_t)w * MSG + lane] = a0 * inv;
    g_y[(size_t)w * MSG + 32 + lane] = a1 * inv;
}

// ---------------- GRU elementwise combine ----------------
__global__ void gru_kernel(const float* __restrict__ zz) {
    int idx = blockIdx.x * blockDim.x + threadIdx.x;
    if (idx >= NAG * CMM) return;
    int n = idx >> 7, j = idx & 127;
    size_t base = (size_t)n * 384;
    float ir = g_gi[base + j],       hr = g_gh[base + j];
    float iz = g_gi[base + 128 + j], hz = g_gh[base + 128 + j];
    float in_ = g_gi[base + 256 + j], hn = g_gh[base + 256 + j];
    float r  = 1.f / (1.f + __expf(-(ir + hr)));
    float zg = 1.f / (1.f + __expf(-(iz + hz)));
    float nn = tanhf(in_ + r * hn);
    g_h[idx] = (1.f - zg) * nn + zg * zz[idx];
}

// ---------------- output head ----------------
__global__ void out_kernel(const float* __restrict__ W, const float* __restrict__ b,
                           float* __restrict__ out) {
    int idx = blockIdx.x * blockDim.x + threadIdx.x;
    if (idx >= NAG * OUTD) return;
    int n = idx / OUTD, j = idx % OUTD;
    const float* hr = g_h + (size_t)n * CMM;
    float s = b[j];
    #pragma unroll 8
    for (int k = 0; k < CMM; k++) s += hr[k] * W[k * OUTD + j];
    out[idx] = s;
}

// ---------------- host launch ----------------
static void gemm(const float* A, const float* B, const float* bias, float* C,
                 int M, int N, int K, int ldb, int flags) {
    dim3 grid((M + 63) / 64, N / 64);
    gemm_k<<<grid, 256>>>(A, B, bias, C, M, N, K, ldb, flags);
}

extern "C" void kernel_launch(void* const* d_in, const int* in_sizes, int n_in,
                              void* d_out, int out_size) {
    const float* feat_gt    = (const float*)d_in[0];
    const float* feat_agent = (const float*)d_in[1];
    const float* z          = (const float*)d_in[2];
    const int*   gt_src     = (const int*)d_in[3];
    const int*   gt_dst     = (const int*)d_in[4];
    const int*   comm_src   = (const int*)d_in[5];
    const int*   comm_dst   = (const int*)d_in[6];
    const float* w1_src     = (const float*)d_in[7];
    const float* w1_dst     = (const float*)d_in[8];
    const float* a1_l       = (const float*)d_in[9];
    const float* a1_r       = (const float*)d_in[10];
    const float* b1         = (const float*)d_in[11];
    const float* w2_src     = (const float*)d_in[12];
    const float* w2_dst     = (const float*)d_in[13];
    const float* a2_l       = (const float*)d_in[14];
    const float* a2_r       = (const float*)d_in[15];
    const float* b2         = (const float*)d_in[16];
    const float* enc_w1     = (const float*)d_in[17];
    const float* enc_b1     = (const float*)d_in[18];
    const float* enc_w2     = (const float*)d_in[19];
    const float* enc_b2     = (const float*)d_in[20];
    const float* gw_ih      = (const float*)d_in[21];
    const float* gw_hh      = (const float*)d_in[22];
    const float* gb_ih      = (const float*)d_in[23];
    const float* gb_hh      = (const float*)d_in[24];
    const float* out_w      = (const float*)d_in[25];
    const float* out_b      = (const float*)d_in[26];

    float *p_fs1, *p_fs2, *p_h, *p_t, *p_m, *p_y, *p_gi, *p_gh;
    cudaGetSymbolAddress((void**)&p_fs1, g_fs1);
    cudaGetSymbolAddress((void**)&p_fs2, g_fs2);
    cudaGetSymbolAddress((void**)&p_h,   g_h);
    cudaGetSymbolAddress((void**)&p_t,   g_t128);
    cudaGetSymbolAddress((void**)&p_m,   g_m);
    cudaGetSymbolAddress((void**)&p_y,   g_y);
    cudaGetSymbolAddress((void**)&p_gi,  g_gi);
    cudaGetSymbolAddress((void**)&p_gh,  g_gh);

    // 1) init + folded dst-attention vectors
    init_kernel<<<(NAG + 255) / 256, 256>>>();
    v12_kernel<<<1, 256>>>(w1_dst, a1_r, w2_dst, a2_r);

    // 2) src projections
    gemm(feat_gt, w1_src, nullptr, p_fs1, NGT, VIS, DGT, VIS, 0);
    gemm(feat_gt, w2_src, nullptr, p_fs2, NGT, CMM, DGT, CMM, 0);

    // 3) per-node attention scalars + global maxima
    el_kernel<<<(2 * NGT * NH + 255) / 256, 256>>>(a1_l, a2_l);
    gmax_kernel<<<296, 256>>>();
    er1_kernel<<<(NAG * NH + 255) / 256, 256>>>(feat_agent);

    // 4) CSR build for both edge lists (merged launches)
    count2_kernel<<<(EGT + ECM + 255) / 256, 256>>>(gt_dst, comm_dst);
    scan2_kernel<<<2, 1024>>>();
    scatter2_kernel<<<(EGT + ECM + 255) / 256, 256>>>(gt_src, gt_dst, comm_src, comm_dst);

    // 5) GAT stage 1 -> dst2, then stage 2 -> h (single-pass each)
    gat1_kernel<<<(NAG * 32 + 255) / 256, 256>>>(feat_agent, b1);
    er2_kernel<<<(NAG * NH + 255) / 256, 256>>>();
    gat2_kernel<<<(NAG * 32 + 255) / 256, 256>>>(b2);

    // 6) two comm steps
    const float* zz = z;
    for (int step = 0; step < 2; step++) {
        gemm(p_h, enc_w1, enc_b1, p_t, NAG, 128, CMM, 128, FLAG_RELU);
        gemm(p_t, enc_w2, enc_b2, p_m, NAG, MSG, 128, MSG, FLAG_RELU);
        comm_agg_kernel<<<(NAG * 32 + 255) / 256, 256>>>();
        // gi = h @ W_ih[0:128] + b_ih ; gi += y @ W_ih[128:192]
        gemm(p_h, gw_ih, gb_ih, p_gi, NAG, 384, CMM, 384, 0);
        gemm(p_y, gw_ih + (size_t)CMM * 384, nullptr, p_gi, NAG, 384, MSG, 384, FLAG_ACC);
        gemm(zz, gw_hh, gb_hh, p_gh, NAG, 384, CMM, 384, 0);
        gru_kernel<<<(NAG * CMM + 255) / 256, 256>>>(zz);
        zz = p_h;   // after update, zz == h
    }

    // 7) outputs: (h_out [NAG,5], zz [NAG,128]) flattened in order
    float* out = (float*)d_out;
    if (out_size == NAG * CMM) {
        cudaMemcpyAsync(out, p_h, (size_t)NAG * CMM * sizeof(float), cudaMemcpyDeviceToDevice);
    } else if (out_size == NAG * OUTD) {
        out_kernel<<<(NAG * OUTD + 255) / 256, 256>>>(out_w, out_b, out);
    } else {
        out_kernel<<<(NAG * OUTD + 255) / 256, 256>>>(out_w, out_b, out);
        cudaMemcpyAsync(out + NAG * OUTD, p_h, (size_t)NAG * CMM * sizeof(float),
                        cudaMemcpyDeviceToDevice);
    }
}

// round 13
// speedup vs baseline: 1.7909x; 1.1432x over previous
#include <cuda_runtime.h>
#include <mma.h>
#include <math.h>

using namespace nvcuda;

// ---------------- problem constants ----------------
#define NGT   100000
#define NAG   20000
#define EGT   640000
#define ECM   320000
#define DGT   32
#define DAG   64
#define VIS   64
#define CMM   128
#define MSG   64
#define OUTD  5
#define NH    4

// ---------------- scratch (device globals; no cudaMalloc allowed) ----------------
__device__ __align__(128) float g_fs1[NGT * VIS];
__device__ __align__(128) float g_el1[NGT * NH];
__device__ __align__(128) float g_fs2[NGT * CMM];
__device__ __align__(128) float g_el2[NGT * NH];
__device__ __align__(128) float g_er1[NAG * NH];
__device__ __align__(128) float g_er2[NAG * NH];
__device__ __align__(128) float g_dst2[NAG * CMM];   // [h_vis1 | feat_agent]
__device__ __align__(128) float g_h[NAG * CMM];
__device__ __align__(128) float g_t128[NAG * CMM];
__device__ __align__(128) float g_m[NAG * MSG];
__device__ __align__(128) float g_y[NAG * MSG];
__device__ __align__(128) float g_gi[NAG * 3 * CMM];
__device__ __align__(128) float g_gh[NAG * 3 * CMM];
__device__ __align__(128) float g_v1[DAG * NH];
__device__ __align__(128) float g_v2[CMM * NH];
__device__ unsigned g_gmx1[NH];
__device__ unsigned g_gmx2[NH];

__device__ int g_cnt_gt[NAG];
__device__ int g_cur_gt[NAG];
__device__ int g_offs_gt[NAG + 1];
__device__ int g_csr_gt[EGT];
__device__ int g_cnt_cm[NAG];
__device__ int g_cur_cm[NAG];
__device__ int g_offs_cm[NAG + 1];
__device__ int g_csr_cm[ECM];

__device__ __forceinline__ float lrelu(float x) { return x >= 0.f ? x : 0.2f * x; }
__device__ __forceinline__ unsigned fkey(float f) {
    unsigned u = __float_as_uint(f);
    return (u & 0x80000000u) ? ~u : (u | 0x80000000u);
}
__device__ __forceinline__ float fdecode(unsigned k) {
    return (k & 0x80000000u) ? __uint_as_float(k & 0x7fffffffu) : __uint_as_float(~k);
}

// ---------------- init: zero counters ----------------
__global__ void init_kernel() {
    int t = blockIdx.x * blockDim.x + threadIdx.x;
    if (t < NAG) { g_cnt_gt[t] = 0; g_cur_gt[t] = 0; g_cnt_cm[t] = 0; g_cur_cm[t] = 0; }
    if (t < NH) { g_gmx1[t] = 0u; g_gmx2[t] = 0u; }
}

// ---------------- fold W_dst @ a_r into v[k][h] ----------------
__global__ void v12_kernel(const float* __restrict__ w1_dst, const float* __restrict__ a1_r,
                           const float* __restrict__ w2_dst, const float* __restrict__ a2_r) {
    int t = threadIdx.x;           // 256 threads, one block
    {   // v1: [64][4], dh=16
        int k = t >> 2, h = t & 3;
        float s = 0.f;
        #pragma unroll
        for (int d = 0; d < 16; d++) s += w1_dst[k * VIS + h * 16 + d] * a1_r[h * 16 + d];
        g_v1[t] = s;
    }
    #pragma unroll
    for (int i = 0; i < 2; i++) {  // v2: [128][4], dh=32
        int idx = t + i * 256;
        int k = idx >> 2, h = idx & 3;
        float s = 0.f;
        #pragma unroll
        for (int d = 0; d < 32; d++) s += w2_dst[k * CMM + h * 32 + d] * a2_r[h * 32 + d];
        g_v2[idx] = s;
    }
}

// ---------------- fp32 tiled SGEMM (used only for src projections) ----------------
#define FLAG_RELU 1
#define FLAG_ACC  2
__global__ void gemm_k(const float* __restrict__ A, const float* __restrict__ B,
                       const float* __restrict__ bias, float* __restrict__ C,
                       int M, int N, int K, int ldb, int flags) {
    __shared__ float As[16][68];
    __shared__ float Bs[16][68];
    int tid = threadIdx.x;
    int row0 = blockIdx.x * 64;
    int col0 = blockIdx.y * 64;
    int ty = tid >> 4, tx = tid & 15;
    float acc[4][4] = {};
    int arow = tid >> 2;
    int acol = (tid & 3) * 4;
    int brow = tid >> 4;
    int bcol = (tid & 15) * 4;

    for (int k0 = 0; k0 < K; k0 += 16) {
        float4 av = make_float4(0.f, 0.f, 0.f, 0.f);
        int gr = row0 + arow;
        if (gr < M) av = *(const float4*)(A + (size_t)gr * K + k0 + acol);
        As[acol + 0][arow] = av.x; As[acol + 1][arow] = av.y;
        As[acol + 2][arow] = av.z; As[acol + 3][arow] = av.w;
        float4 bv = *(const float4*)(B + (size_t)(k0 + brow) * ldb + col0 + bcol);
        *(float4*)&Bs[brow][bcol] = bv;
        __syncthreads();
        #pragma unroll
        for (int k = 0; k < 16; k++) {
            float4 a = *(float4*)&As[k][ty * 4];
            float4 b = *(float4*)&Bs[k][tx * 4];
            acc[0][0] += a.x * b.x; acc[0][1] += a.x * b.y; acc[0][2] += a.x * b.z; acc[0][3] += a.x * b.w;
            acc[1][0] += a.y * b.x; acc[1][1] += a.y * b.y; acc[1][2] += a.y * b.z; acc[1][3] += a.y * b.w;
            acc[2][0] += a.z * b.x; acc[2][1] += a.z * b.y; acc[2][2] += a.z * b.z; acc[2][3] += a.z * b.w;
            acc[3][0] += a.w * b.x; acc[3][1] += a.w * b.y; acc[3][2] += a.w * b.z; acc[3][3] += a.w * b.w;
        }
        __syncthreads();
    }
    int c0 = col0 + tx * 4;
    #pragma unroll
    for (int i = 0; i < 4; i++) {
        int r = row0 + ty * 4 + i;
        if (r < M) {
            float4 v = make_float4(acc[i][0], acc[i][1], acc[i][2], acc[i][3]);
            float* cp = C + (size_t)r * N + c0;
            if (bias) {
                v.x += bias[c0]; v.y += bias[c0 + 1]; v.z += bias[c0 + 2]; v.w += bias[c0 + 3];
            }
            if (flags & FLAG_RELU) {
                v.x = fmaxf(v.x, 0.f); v.y = fmaxf(v.y, 0.f); v.z = fmaxf(v.z, 0.f); v.w = fmaxf(v.w, 0.f);
            }
            *(float4*)cp = v;
        }
    }
}

// ---------------- TF32 tensor-core GEMM: 128x64 block tile, 8 warps x (32x32) ----------------
// C[M,N] = act(A[M,K] @ B[K,N] + bias [+C]); K % 16 == 0, N % 64 == 0, ldb == N.
// Epilogue staging Cs (row stride 36, multiple of 4: wmma ldm legal + float4 aligned)
// overlaps the mainloop As/Bs tiles via a union — safe because the last mainloop
// iteration ends with __syncthreads(), after which As/Bs are never read.
__global__ __launch_bounds__(256)
void gemm_tc(const float* __restrict__ A, const float* __restrict__ B,
             const float* __restrict__ bias, float* __restrict__ C,
             int M, int N, int K, int flags) {
    __shared__ union SU {
        struct {
            float As[128][20];      // [m][k], 16 k + pad
            float Bs[16][68];       // [k][n]
        } in;
        float Cs[8][32][36];        // per-warp epilogue staging
    } sm;

    int tid = threadIdx.x;
    int wid = tid >> 5, lane = tid & 31;
    int wr = wid >> 1, wc = wid & 1;    // warp tile: rows wr*32, cols wc*32
    int row0 = blockIdx.x * 128;
    int col0 = blockIdx.y * 64;

    // staging indices
    int a_row = tid >> 1;                 // 0..127
    int a_kp  = (tid & 1) * 8;            // 0 or 8
    int a_gr  = min(row0 + a_row, M - 1);
    int b_kr  = tid >> 4;                 // 0..15
    int b_c   = (tid & 15) * 4;           // 0..60

    wmma::fragment<wmma::accumulator, 16, 16, 8, float> cfr[2][2];
    #pragma unroll
    for (int i = 0; i < 2; i++)
        #pragma unroll
        for (int j = 0; j < 2; j++) wmma::fill_fragment(cfr[i][j], 0.f);

    for (int k0 = 0; k0 < K; k0 += 16) {
        float4 av0 = *(const float4*)(A + (size_t)a_gr * K + k0 + a_kp);
        float4 av1 = *(const float4*)(A + (size_t)a_gr * K + k0 + a_kp + 4);
        float4 bv  = *(const float4*)(B + (size_t)(k0 + b_kr) * N + col0 + b_c);
        *(float4*)&sm.in.As[a_row][a_kp]     = av0;
        *(float4*)&sm.in.As[a_row][a_kp + 4] = av1;
        *(float4*)&sm.in.Bs[b_kr][b_c]       = bv;
        __syncthreads();

        #pragma unroll
        for (int kk = 0; kk < 16; kk += 8) {
            wmma::fragment<wmma::matrix_a, 16, 16, 8, wmma::precision::tf32, wmma::row_major> afr[2];
            wmma::fragment<wmma::matrix_b, 16, 16, 8, wmma::precision::tf32, wmma::row_major> bfr[2];
            wmma::load_matrix_sync(afr[0], &sm.in.As[wr * 32][kk], 20);
            wmma::load_matrix_sync(afr[1], &sm.in.As[wr * 32 + 16][kk], 20);
            wmma::load_matrix_sync(bfr[0], &sm.in.Bs[kk][wc * 32], 68);
            wmma::load_matrix_sync(bfr[1], &sm.in.Bs[kk][wc * 32 + 16], 68);
            #pragma unroll
            for (int t = 0; t < afr[0].num_elements; t++) {
                afr[0].x[t] = wmma::__float_to_tf32(afr[0].x[t]);
                afr[1].x[t] = wmma::__float_to_tf32(afr[1].x[t]);
            }
            #pragma unroll
            for (int t = 0; t < bfr[0].num_elements; t++) {
                bfr[0].x[t] = wmma::__float_to_tf32(bfr[0].x[t]);
                bfr[1].x[t] = wmma::__float_to_tf32(bfr[1].x[t]);
            }
            #pragma unroll
            for (int i = 0; i < 2; i++)
                #pragma unroll
                for (int j = 0; j < 2; j++)
                    wmma::mma_sync(cfr[i][j], afr[i], bfr[j], cfr[i][j]);
        }
        __syncthreads();
    }

    // epilogue: stage 32x32 per warp into Cs (overlaps As/Bs; all reads done)
    #pragma unroll
    for (int i = 0; i < 2; i++)
        #pragma unroll
        for (int j = 0; j < 2; j++)
            wmma::store_matrix_sync(&sm.Cs[wid][i * 16][j * 16], cfr[i][j], 36, wmma::mem_row_major);
    __syncwarp();

    int lcol = (lane & 7) * 4;            // 0..28
    int lrow = lane >> 3;                 // 0..3
    int cbase = col0 + wc * 32 + lcol;
    float4 bz = make_float4(0.f, 0.f, 0.f, 0.f);
    if (bias) bz = *(const float4*)(bias + cbase);
    #pragma unroll
    for (int it = 0; it < 8; it++) {
        int rr = it * 4 + lrow;           // 0..31
        int r = row0 + wr * 32 + rr;
        if (r >= M) continue;
        float4 v = *(float4*)&sm.Cs[wid][rr][lcol];
        float* cp = C + (size_t)r * N + cbase;
        if (flags & FLAG_ACC) {
            float4 o = *(const float4*)cp;
            v.x += o.x; v.y += o.y; v.z += o.z; v.w += o.w;
        }
        v.x += bz.x; v.y += bz.y; v.z += bz.z; v.w += bz.w;
        if (flags & FLAG_RELU) {
            v.x = fmaxf(v.x, 0.f); v.y = fmaxf(v.y, 0.f);
            v.z = fmaxf(v.z, 0.f); v.w = fmaxf(v.w, 0.f);
        }
        *(float4*)cp = v;
    }
}

// ---------------- el = sum over dh of fs * a_l ----------------
__global__ void el_kernel(const float* __restrict__ a1l, const float* __restrict__ a2l) {
    int t = blockIdx.x * blockDim.x + threadIdx.x;
    if (t < NGT * NH) {
        int i = t >> 2, h = t & 3;
        const float* f = g_fs1 + (size_t)i * VIS + h * 16;
        const float* a = a1l + h * 16;
        float s = 0.f;
        #pragma unroll
        for (int d = 0; d < 16; d++) s += f[d] * a[d];
        g_el1[t] = s;
    } else if (t < 2 * NGT * NH) {
        int u = t - NGT * NH;
        int i = u >> 2, h = u & 3;
        const float* f = g_fs2 + (size_t)i * CMM + h * 32;
        const float* a = a2l + h * 32;
        float s = 0.f;
        #pragma unroll
        for (int d = 0; d < 32; d++) s += f[d] * a[d];
        g_el2[u] = s;
    }
}

// ---------------- global per-head max of el1/el2 ----------------
__global__ void gmax_kernel() {
    __shared__ unsigned s1[4], s2[4];
    int tid = threadIdx.x;
    if (tid < 4) { s1[tid] = 0u; s2[tid] = 0u; }
    __syncthreads();
    unsigned l1[4] = {0u, 0u, 0u, 0u}, l2[4] = {0u, 0u, 0u, 0u};
    for (int i = blockIdx.x * blockDim.x + tid; i < NGT; i += gridDim.x * blockDim.x) {
        float4 e1 = *(const float4*)&g_el1[i * 4];
        float4 e2 = *(const float4*)&g_el2[i * 4];
        l1[0] = max(l1[0], fkey(e1.x)); l1[1] = max(l1[1], fkey(e1.y));
        l1[2] = max(l1[2], fkey(e1.z)); l1[3] = max(l1[3], fkey(e1.w));
        l2[0] = max(l2[0], fkey(e2.x)); l2[1] = max(l2[1], fkey(e2.y));
        l2[2] = max(l2[2], fkey(e2.z)); l2[3] = max(l2[3], fkey(e2.w));
    }
    #pragma unroll
    for (int h = 0; h < 4; h++) { atomicMax(&s1[h], l1[h]); atomicMax(&s2[h], l2[h]); }
    __syncthreads();
    if (tid < 4) { atomicMax(&g_gmx1[tid], s1[tid]); atomicMax(&g_gmx2[tid], s2[tid]); }
}

// ---------------- er1 = feat_agent @ v1 ----------------
__global__ void er1_kernel(const float* __restrict__ feat_agent) {
    int t = blockIdx.x * blockDim.x + threadIdx.x;
    if (t >= NAG * NH) return;
    int n = t >> 2, h = t & 3;
    const float* f = feat_agent + (size_t)n * DAG;
    float s = 0.f;
    #pragma unroll 8
    for (int k = 0; k < DAG; k++) s += f[k] * g_v1[k * NH + h];
    g_er1[t] = s;
}

// ---------------- er2 = dst2 @ v2 ----------------
__global__ void er2_kernel() {
    int t = blockIdx.x * blockDim.x + threadIdx.x;
    if (t >= NAG * NH) return;
    int n = t >> 2, h = t & 3;
    const float* f = g_dst2 + (size_t)n * CMM;
    float s = 0.f;
    #pragma unroll 8
    for (int k = 0; k < CMM; k++) s += f[k] * g_v2[k * NH + h];
    g_er2[t] = s;
}

// ---------------- CSR build (merged launches) ----------------
__global__ void count2_kernel(const int* __restrict__ gt_dst, const int* __restrict__ cm_dst) {
    int e = blockIdx.x * blockDim.x + threadIdx.x;
    if (e < EGT) atomicAdd(&g_cnt_gt[gt_dst[e]], 1);
    else if (e < EGT + ECM) atomicAdd(&g_cnt_cm[cm_dst[e - EGT]], 1);
}

__device__ void scan_body(const int* __restrict__ cnt, int* __restrict__ offs, int n) {
    __shared__ int wsum[32];
    __shared__ int carry;
    int tid = threadIdx.x, lane = tid & 31, wid = tid >> 5;
    if (tid == 0) carry = 0;
    __syncthreads();
    for (int base = 0; base < n; base += 1024) {
        int i = base + tid;
        int v = (i < n) ? cnt[i] : 0;
        int x = v;
        #pragma unroll
        for (int off = 1; off < 32; off <<= 1) {
            int t = __shfl_up_sync(0xffffffffu, x, off);
            if (lane >= off) x += t;
        }
        if (lane == 31) wsum[wid] = x;
        __syncthreads();
        if (wid == 0) {
            int s = wsum[lane];
            #pragma unroll
            for (int off = 1; off < 32; off <<= 1) {
                int t = __shfl_up_sync(0xffffffffu, s, off);
                if (lane >= off) s += t;
            }
            wsum[lane] = s;
        }
        __syncthreads();
        int wpre = (wid > 0) ? wsum[wid - 1] : 0;
        int incl = carry + wpre + x;
        if (i < n) offs[i] = incl - v;
        __syncthreads();
        if (tid == 1023) carry = incl;
        __syncthreads();
    }
    if (tid == 0) offs[n] = carry;
}

__global__ void scan2_kernel() {
    if (blockIdx.x == 0) scan_body(g_cnt_gt, g_offs_gt, NAG);
    else                 scan_body(g_cnt_cm, g_offs_cm, NAG);
}

__global__ void scatter2_kernel(const int* __restrict__ gt_src, const int* __restrict__ gt_dst,
                                const int* __restrict__ cm_src, const int* __restrict__ cm_dst) {
    int e = blockIdx.x * blockDim.x + threadIdx.x;
    if (e < EGT) {
        int d = gt_dst[e];
        int p = atomicAdd(&g_cur_gt[d], 1);
        g_csr_gt[g_offs_gt[d] + p] = gt_src[e];
    } else if (e < EGT + ECM) {
        int e2 = e - EGT;
        int d = cm_dst[e2];
        int p = atomicAdd(&g_cur_cm[d], 1);
        g_csr_cm[g_offs_cm[d] + p] = cm_src[e2];
    }
}

// ---------------- GAT1: single-pass softmax via global shift (warp per dst) ----------------
__global__ void gat1_kernel(const float* __restrict__ feat_agent, const float* __restrict__ b1) {
    int w = (blockIdx.x * blockDim.x + threadIdx.x) >> 5;
    if (w >= NAG) return;
    int lane = threadIdx.x & 31;
    int beg = g_offs_gt[w], end = g_offs_gt[w + 1];
    float4 er = *(const float4*)&g_er1[w * 4];
    float m0 = lrelu(fdecode(g_gmx1[0]) + er.x);
    float m1 = lrelu(fdecode(g_gmx1[1]) + er.y);
    float m2 = lrelu(fdecode(g_gmx1[2]) + er.z);
    float m3 = lrelu(fdecode(g_gmx1[3]) + er.w);
    float d0 = 0.f, d1 = 0.f, d2 = 0.f, d3 = 0.f;
    float acc0 = 0.f, acc1 = 0.f;
    int hs = lane >> 4;
    for (int e = beg; e < end; e++) {
        int s = g_csr_gt[e];
        float4 el = *(const float4*)&g_el1[s * 4];
        float p0 = __expf(lrelu(el.x + er.x) - m0);
        float p1 = __expf(lrelu(el.y + er.y) - m1);
        float p2 = __expf(lrelu(el.z + er.z) - m2);
        float p3 = __expf(lrelu(el.w + er.w) - m3);
        d0 += p0; d1 += p1; d2 += p2; d3 += p3;
        float pa = (hs == 0) ? p0 : p1;
        float pb = (hs == 0) ? p2 : p3;
        const float* fr = g_fs1 + (size_t)s * VIS;
        acc0 += pa * fr[lane];
        acc1 += pb * fr[32 + lane];
    }
    float da = (hs == 0) ? d0 : d1;
    float db = (hs == 0) ? d2 : d3;
    float ia = da > 0.f ? 1.f / da : 0.f;
    float ib = db > 0.f ? 1.f / db : 0.f;
    float fa0 = feat_agent[(size_t)w * DAG + lane];
    float fa1 = feat_agent[(size_t)w * DAG + 32 + lane];
    float o0 = fmaxf(acc0 * ia + fa0 + b1[lane], 0.f);
    float o1 = fmaxf(acc1 * ib + fa1 + b1[32 + lane], 0.f);
    float* dr = g_dst2 + (size_t)w * CMM;
    dr[lane] = o0; dr[32 + lane] = o1;
    dr[64 + lane] = fa0; dr[96 + lane] = fa1;
}

// ---------------- GAT2: single-pass softmax via global shift ----------------
__global__ void gat2_kernel(const float* __restrict__ b2) {
    int w = (blockIdx.x * blockDim.x + threadIdx.x) >> 5;
    if (w >= NAG) return;
    int lane = threadIdx.x & 31;
    int beg = g_offs_gt[w], end = g_offs_gt[w + 1];
    float4 er = *(const float4*)&g_er2[w * 4];
    float m0 = lrelu(fdecode(g_gmx2[0]) + er.x);
    float m1 = lrelu(fdecode(g_gmx2[1]) + er.y);
    float m2 = lrelu(fdecode(g_gmx2[2]) + er.z);
    float m3 = lrelu(fdecode(g_gmx2[3]) + er.w);
    float d0 = 0.f, d1 = 0.f, d2 = 0.f, d3 = 0.f;
    float a0 = 0.f, a1 = 0.f, a2 = 0.f, a3 = 0.f;
    for (int e = beg; e < end; e++) {
        int s = g_csr_gt[e];
        float4 el = *(const float4*)&g_el2[s * 4];
        float p0 = __expf(lrelu(el.x + er.x) - m0);
        float p1 = __expf(lrelu(el.y + er.y) - m1);
        float p2 = __expf(lrelu(el.z + er.z) - m2);
        float p3 = __expf(lrelu(el.w + er.w) - m3);
        d0 += p0; d1 += p1; d2 += p2; d3 += p3;
        const float* fr = g_fs2 + (size_t)s * CMM;
        a0 += p0 * fr[lane];
        a1 += p1 * fr[32 + lane];
        a2 += p2 * fr[64 + lane];
        a3 += p3 * fr[96 + lane];
    }
    float i0 = d0 > 0.f ? 1.f / d0 : 0.f;
    float i1 = d1 > 0.f ? 1.f / d1 : 0.f;
    float i2 = d2 > 0.f ? 1.f / d2 : 0.f;
    float i3 = d3 > 0.f ? 1.f / d3 : 0.f;
    const float* dr = g_dst2 + (size_t)w * CMM;
    float* hr = g_h + (size_t)w * CMM;
    hr[lane]      = fmaxf(a0 * i0 + dr[lane]      + b2[lane],      0.f);
    hr[32 + lane] = fmaxf(a1 * i1 + dr[32 + lane] + b2[32 + lane], 0.f);
    hr[64 + lane] = fmaxf(a2 * i2 + dr[64 + lane] + b2[64 + lane], 0.f);
    hr[96 + lane] = fmaxf(a3 * i3 + dr[96 + lane] + b2[96 + lane], 0.f);
}

// ---------------- comm mailbox mean ----------------
__global__ void comm_agg_kernel() {
    int w = (blockIdx.x * blockDim.x + threadIdx.x) >> 5;
    if (w >= NAG) return;
    int lane = threadIdx.x & 31;
    int beg = g_offs_cm[w], end = g_offs_cm[w + 1];
    float a0 = 0.f, a1 = 0.f;
    for (int e = beg; e < end; e++) {
        int s = g_csr_cm[e];
        const float* mr = g_m + (size_t)s * MSG;
        a0 += mr[lane];
        a1 += mr[32 + lane];
    }
    int deg = end - beg;
    float inv = 1.f / (float)(deg > 0 ? deg : 1);
    g_y[(size_t)w * MSG + lane] = a0 * inv;
    g_y[(size_t)w * MSG + 32 + lane] = a1 * inv;
}

// ---------------- GRU elementwise combine ----------------
__global__ void gru_kernel(const float* __restrict__ zz) {
    int idx = blockIdx.x * blockDim.x + threadIdx.x;
    if (idx >= NAG * CMM) return;
    int n = idx >> 7, j = idx & 127;
    size_t base = (size_t)n * 384;
    float ir = g_gi[base + j],       hr = g_gh[base + j];
    float iz = g_gi[base + 128 + j], hz = g_gh[base + 128 + j];
    float in_ = g_gi[base + 256 + j], hn = g_gh[base + 256 + j];
    float r  = 1.f / (1.f + __expf(-(ir + hr)));
    float zg = 1.f / (1.f + __expf(-(iz + hz)));
    float nn = tanhf(in_ + r * hn);
    g_h[idx] = (1.f - zg) * nn + zg * zz[idx];
}

// ---------------- output head ----------------
__global__ void out_kernel(const float* __restrict__ W, const float* __restrict__ b,
                           float* __restrict__ out) {
    int idx = blockIdx.x * blockDim.x + threadIdx.x;
    if (idx >= NAG * OUTD) return;
    int n = idx / OUTD, j = idx % OUTD;
    const float* hr = g_h + (size_t)n * CMM;
    float s = b[j];
    #pragma unroll 8
    for (int k = 0; k < CMM; k++) s += hr[k] * W[k * OUTD + j];
    out[idx] = s;
}

// ---------------- host launch ----------------
static void gemm(const float* A, const float* B, const float* bias, float* C,
                 int M, int N, int K, int ldb, int flags) {
    dim3 grid((M + 63) / 64, N / 64);
    gemm_k<<<grid, 256>>>(A, B, bias, C, M, N, K, ldb, flags);
}

static void gemm_tf32(const float* A, const float* B, const float* bias, float* C,
                      int M, int N, int K, int flags) {
    dim3 grid((M + 127) / 128, N / 64);
    gemm_tc<<<grid, 256>>>(A, B, bias, C, M, N, K, flags);
}

extern "C" void kernel_launch(void* const* d_in, const int* in_sizes, int n_in,
                              void* d_out, int out_size) {
    const float* feat_gt    = (const float*)d_in[0];
    const float* feat_agent = (const float*)d_in[1];
    const float* z          = (const float*)d_in[2];
    const int*   gt_src     = (const int*)d_in[3];
    const int*   gt_dst     = (const int*)d_in[4];
    const int*   comm_src   = (const int*)d_in[5];
    const int*   comm_dst   = (const int*)d_in[6];
    const float* w1_src     = (const float*)d_in[7];
    const float* w1_dst     = (const float*)d_in[8];
    const float* a1_l       = (const float*)d_in[9];
    const float* a1_r       = (const float*)d_in[10];
    const float* b1         = (const float*)d_in[11];
    const float* w2_src     = (const float*)d_in[12];
    const float* w2_dst     = (const float*)d_in[13];
    const float* a2_l       = (const float*)d_in[14];
    const float* a2_r       = (const float*)d_in[15];
    const float* b2         = (const float*)d_in[16];
    const float* enc_w1     = (const float*)d_in[17];
    const float* enc_b1     = (const float*)d_in[18];
    const float* enc_w2     = (const float*)d_in[19];
    const float* enc_b2     = (const float*)d_in[20];
    const float* gw_ih      = (const float*)d_in[21];
    const float* gw_hh      = (const float*)d_in[22];
    const float* gb_ih      = (const float*)d_in[23];
    const float* gb_hh      = (const float*)d_in[24];
    const float* out_w      = (const float*)d_in[25];
    const float* out_b      = (const float*)d_in[26];

    float *p_fs1, *p_fs2, *p_h, *p_t, *p_m, *p_y, *p_gi, *p_gh;
    cudaGetSymbolAddress((void**)&p_fs1, g_fs1);
    cudaGetSymbolAddress((void**)&p_fs2, g_fs2);
    cudaGetSymbolAddress((void**)&p_h,   g_h);
    cudaGetSymbolAddress((void**)&p_t,   g_t128);
    cudaGetSymbolAddress((void**)&p_m,   g_m);
    cudaGetSymbolAddress((void**)&p_y,   g_y);
    cudaGetSymbolAddress((void**)&p_gi,  g_gi);
    cudaGetSymbolAddress((void**)&p_gh,  g_gh);

    // 1) init + folded dst-attention vectors
    init_kernel<<<(NAG + 255) / 256, 256>>>();
    v12_kernel<<<1, 256>>>(w1_dst, a1_r, w2_dst, a2_r);

    // 2) src projections (fp32 — feed attention scores)
    gemm(feat_gt, w1_src, nullptr, p_fs1, NGT, VIS, DGT, VIS, 0);
    gemm(feat_gt, w2_src, nullptr, p_fs2, NGT, CMM, DGT, CMM, 0);

    // 3) per-node attention scalars + global maxima
    el_kernel<<<(2 * NGT * NH + 255) / 256, 256>>>(a1_l, a2_l);
    gmax_kernel<<<296, 256>>>();
    er1_kernel<<<(NAG * NH + 255) / 256, 256>>>(feat_agent);

    // 4) CSR build for both edge lists (merged launches)
    count2_kernel<<<(EGT + ECM + 255) / 256, 256>>>(gt_dst, comm_dst);
    scan2_kernel<<<2, 1024>>>();
    scatter2_kernel<<<(EGT + ECM + 255) / 256, 256>>>(gt_src, gt_dst, comm_src, comm_dst);

    // 5) GAT stage 1 -> dst2, then stage 2 -> h (single-pass each)
    gat1_kernel<<<(NAG * 32 + 255) / 256, 256>>>(feat_agent, b1);
    er2_kernel<<<(NAG * NH + 255) / 256, 256>>>();
    gat2_kernel<<<(NAG * 32 + 255) / 256, 256>>>(b2);

    // 6) two comm steps (tf32 tensor-core GEMMs)
    const float* zz = z;
    for (int step = 0; step < 2; step++) {
        gemm_tf32(p_h, enc_w1, enc_b1, p_t, NAG, 128, CMM, FLAG_RELU);
        gemm_tf32(p_t, enc_w2, enc_b2, p_m, NAG, MSG, 128, FLAG_RELU);
        comm_agg_kernel<<<(NAG * 32 + 255) / 256, 256>>>();
        // gi = h @ W_ih[0:128] + b_ih ; gi += y @ W_ih[128:192]
        gemm_tf32(p_h, gw_ih, gb_ih, p_gi, NAG, 384, CMM, 0);
        gemm_tf32(p_y, gw_ih + (size_t)CMM * 384, nullptr, p_gi, NAG, 384, MSG, FLAG_ACC);
        gemm_tf32(zz, gw_hh, gb_hh, p_gh, NAG, 384, CMM, 0);
        gru_kernel<<<(NAG * CMM + 255) / 256, 256>>>(zz);
        zz = p_h;   // after update, zz == h
    }

    // 7) outputs: (h_out [NAG,5], zz [NAG,128]) flattened in order
    float* out = (float*)d_out;
    if (out_size == NAG * CMM) {
        cudaMemcpyAsync(out, p_h, (size_t)NAG * CMM * sizeof(float), cudaMemcpyDeviceToDevice);
    } else if (out_size == NAG * OUTD) {
        out_kernel<<<(NAG * OUTD + 255) / 256, 256>>>(out_w, out_b, out);
    } else {
        out_kernel<<<(NAG * OUTD + 255) / 256, 256>>>(out_w, out_b, out);
        cudaMemcpyAsync(out + NAG * OUTD, p_h, (size_t)NAG * CMM * sizeof(float),
                        cudaMemcpyDeviceToDevice);
    }
}

// round 15
// speedup vs baseline: 1.8873x; 1.0539x over previous
#include <cuda_runtime.h>
#include <mma.h>
#include <math.h>

using namespace nvcuda;

// ---------------- problem constants ----------------
#define NGT   100000
#define NAG   20000
#define EGT   640000
#define ECM   320000
#define DGT   32
#define DAG   64
#define VIS   64
#define CMM   128
#define MSG   64
#define OUTD  5
#define NH    4

// ---------------- scratch (device globals; no cudaMalloc allowed) ----------------
__device__ __align__(128) float g_fs1[NGT * VIS];
__device__ __align__(128) float g_el1[NGT * NH];
__device__ __align__(128) float g_fs2[NGT * CMM];
__device__ __align__(128) float g_el2[NGT * NH];
__device__ __align__(128) float g_er1[NAG * NH];
__device__ __align__(128) float g_er2[NAG * NH];
__device__ __align__(128) float g_dst2[NAG * CMM];   // [h_vis1 | feat_agent]
__device__ __align__(128) float g_h[NAG * CMM];
__device__ __align__(128) float g_t128[NAG * CMM];
__device__ __align__(128) float g_m[NAG * MSG];
__device__ __align__(128) float g_y[NAG * MSG];
__device__ __align__(128) float g_gi[NAG * 3 * CMM];
__device__ __align__(128) float g_gh[NAG * 3 * CMM];
__device__ __align__(128) float g_v1[DAG * NH];
__device__ __align__(128) float g_v2[CMM * NH];
__device__ unsigned g_gmx1[NH];
__device__ unsigned g_gmx2[NH];

__device__ int g_cnt_gt[NAG];
__device__ int g_cur_gt[NAG];
__device__ int g_offs_gt[NAG + 1];
__device__ int g_csr_gt[EGT];
__device__ int g_cnt_cm[NAG];
__device__ int g_cur_cm[NAG];
__device__ int g_offs_cm[NAG + 1];
__device__ int g_csr_cm[ECM];

__device__ __forceinline__ float lrelu(float x) { return x >= 0.f ? x : 0.2f * x; }
__device__ __forceinline__ unsigned fkey(float f) {
    unsigned u = __float_as_uint(f);
    return (u & 0x80000000u) ? ~u : (u | 0x80000000u);
}
__device__ __forceinline__ float fdecode(unsigned k) {
    return (k & 0x80000000u) ? __uint_as_float(k & 0x7fffffffu) : __uint_as_float(~k);
}

// ---------------- init: zero counters ----------------
__global__ void init_kernel() {
    int t = blockIdx.x * blockDim.x + threadIdx.x;
    if (t < NAG) { g_cnt_gt[t] = 0; g_cur_gt[t] = 0; g_cnt_cm[t] = 0; g_cur_cm[t] = 0; }
    if (t < NH) { g_gmx1[t] = 0u; g_gmx2[t] = 0u; }
}

// ---------------- fold W_dst @ a_r into v[k][h] ----------------
__global__ void v12_kernel(const float* __restrict__ w1_dst, const float* __restrict__ a1_r,
                           const float* __restrict__ w2_dst, const float* __restrict__ a2_r) {
    int t = threadIdx.x;           // 256 threads, one block
    {   // v1: [64][4], dh=16
        int k = t >> 2, h = t & 3;
        float s = 0.f;
        #pragma unroll
        for (int d = 0; d < 16; d++) s += w1_dst[k * VIS + h * 16 + d] * a1_r[h * 16 + d];
        g_v1[t] = s;
    }
    #pragma unroll
    for (int i = 0; i < 2; i++) {  // v2: [128][4], dh=32
        int idx = t + i * 256;
        int k = idx >> 2, h = idx & 3;
        float s = 0.f;
        #pragma unroll
        for (int d = 0; d < 32; d++) s += w2_dst[k * CMM + h * 32 + d] * a2_r[h * 32 + d];
        g_v2[idx] = s;
    }
}

// ---------------- fp32 tiled SGEMM (used only for src projections) ----------------
#define FLAG_RELU 1
__global__ void gemm_k(const float* __restrict__ A, const float* __restrict__ B,
                       const float* __restrict__ bias, float* __restrict__ C,
                       int M, int N, int K, int ldb, int flags) {
    __shared__ float As[16][68];
    __shared__ float Bs[16][68];
    int tid = threadIdx.x;
    int row0 = blockIdx.x * 64;
    int col0 = blockIdx.y * 64;
    int ty = tid >> 4, tx = tid & 15;
    float acc[4][4] = {};
    int arow = tid >> 2;
    int acol = (tid & 3) * 4;
    int brow = tid >> 4;
    int bcol = (tid & 15) * 4;

    for (int k0 = 0; k0 < K; k0 += 16) {
        float4 av = make_float4(0.f, 0.f, 0.f, 0.f);
        int gr = row0 + arow;
        if (gr < M) av = *(const float4*)(A + (size_t)gr * K + k0 + acol);
        As[acol + 0][arow] = av.x; As[acol + 1][arow] = av.y;
        As[acol + 2][arow] = av.z; As[acol + 3][arow] = av.w;
        float4 bv = *(const float4*)(B + (size_t)(k0 + brow) * ldb + col0 + bcol);
        *(float4*)&Bs[brow][bcol] = bv;
        __syncthreads();
        #pragma unroll
        for (int k = 0; k < 16; k++) {
            float4 a = *(float4*)&As[k][ty * 4];
            float4 b = *(float4*)&Bs[k][tx * 4];
            acc[0][0] += a.x * b.x; acc[0][1] += a.x * b.y; acc[0][2] += a.x * b.z; acc[0][3] += a.x * b.w;
            acc[1][0] += a.y * b.x; acc[1][1] += a.y * b.y; acc[1][2] += a.y * b.z; acc[1][3] += a.y * b.w;
            acc[2][0] += a.z * b.x; acc[2][1] += a.z * b.y; acc[2][2] += a.z * b.z; acc[2][3] += a.z * b.w;
            acc[3][0] += a.w * b.x; acc[3][1] += a.w * b.y; acc[3][2] += a.w * b.z; acc[3][3] += a.w * b.w;
        }
        __syncthreads();
    }
    int c0 = col0 + tx * 4;
    #pragma unroll
    for (int i = 0; i < 4; i++) {
        int r = row0 + ty * 4 + i;
        if (r < M) {
            float4 v = make_float4(acc[i][0], acc[i][1], acc[i][2], acc[i][3]);
            float* cp = C + (size_t)r * N + c0;
            if (bias) {
                v.x += bias[c0]; v.y += bias[c0 + 1]; v.z += bias[c0 + 2]; v.w += bias[c0 + 3];
            }
            if (flags & FLAG_RELU) {
                v.x = fmaxf(v.x, 0.f); v.y = fmaxf(v.y, 0.f); v.z = fmaxf(v.z, 0.f); v.w = fmaxf(v.w, 0.f);
            }
            *(float4*)cp = v;
        }
    }
}

// ---------------- TF32 tensor-core GEMM, two-phase K (optional A2) ----------------
// C[M,N] = act( A[M,K1] @ B[0:K1,N] + A2[M,K2] @ B[K1:K1+K2,N] + bias );
// 128x64 block tile, 8 warps x (32x32). K1,K2 % 16 == 0, N % 64 == 0, ldb == N.
// tf32 conversion happens ONCE at smem staging (inner loop is pure LDS+MMA).
// Epilogue staging Cs (row stride 36) overlaps As/Bs via union — safe: last
// mainloop iteration ends with __syncthreads(), after which As/Bs are dead.
__device__ __forceinline__ float4 to_tf32_4(float4 v) {
    v.x = wmma::__float_to_tf32(v.x); v.y = wmma::__float_to_tf32(v.y);
    v.z = wmma::__float_to_tf32(v.z); v.w = wmma::__float_to_tf32(v.w);
    return v;
}

__global__ __launch_bounds__(256)
void gemm_tc(const float* __restrict__ A, const float* __restrict__ A2,
             const float* __restrict__ B,
             const float* __restrict__ bias, float* __restrict__ C,
             int M, int N, int K1, int K2, int flags) {
    __shared__ union SU {
        struct {
            float As[128][20];      // [m][k], 16 k + pad
            float Bs[16][68];       // [k][n]
        } in;
        float Cs[8][32][36];        // per-warp epilogue staging
    } sm;

    int tid = threadIdx.x;
    int wid = tid >> 5, lane = tid & 31;
    int wr = wid >> 1, wc = wid & 1;    // warp tile: rows wr*32, cols wc*32
    int row0 = blockIdx.x * 128;
    int col0 = blockIdx.y * 64;

    // staging indices
    int a_row = tid >> 1;                 // 0..127
    int a_kp  = (tid & 1) * 8;            // 0 or 8
    int a_gr  = min(row0 + a_row, M - 1);
    int b_kr  = tid >> 4;                 // 0..15
    int b_c   = (tid & 15) * 4;           // 0..60

    wmma::fragment<wmma::accumulator, 16, 16, 8, float> cfr[2][2];
    #pragma unroll
    for (int i = 0; i < 2; i++)
        #pragma unroll
        for (int j = 0; j < 2; j++) wmma::fill_fragment(cfr[i][j], 0.f);

    int Ktot = K1 + K2;
    for (int k0 = 0; k0 < Ktot; k0 += 16) {
        // phase select (16-tiles never straddle: K1 % 16 == 0)
        const float* ap;
        if (k0 < K1) ap = A  + (size_t)a_gr * K1 + k0;
        else         ap = A2 + (size_t)a_gr * K2 + (k0 - K1);
        float4 av0 = to_tf32_4(*(const float4*)(ap + a_kp));
        float4 av1 = to_tf32_4(*(const float4*)(ap + a_kp + 4));
        float4 bv  = to_tf32_4(*(const float4*)(B + (size_t)(k0 + b_kr) * N + col0 + b_c));
        *(float4*)&sm.in.As[a_row][a_kp]     = av0;
        *(float4*)&sm.in.As[a_row][a_kp + 4] = av1;
        *(float4*)&sm.in.Bs[b_kr][b_c]       = bv;
        __syncthreads();

        #pragma unroll
        for (int kk = 0; kk < 16; kk += 8) {
            wmma::fragment<wmma::matrix_a, 16, 16, 8, wmma::precision::tf32, wmma::row_major> afr[2];
            wmma::fragment<wmma::matrix_b, 16, 16, 8, wmma::precision::tf32, wmma::row_major> bfr[2];
            wmma::load_matrix_sync(afr[0], &sm.in.As[wr * 32][kk], 20);
            wmma::load_matrix_sync(afr[1], &sm.in.As[wr * 32 + 16][kk], 20);
            wmma::load_matrix_sync(bfr[0], &sm.in.Bs[kk][wc * 32], 68);
            wmma::load_matrix_sync(bfr[1], &sm.in.Bs[kk][wc * 32 + 16], 68);
            #pragma unroll
            for (int i = 0; i < 2; i++)
                #pragma unroll
                for (int j = 0; j < 2; j++)
                    wmma::mma_sync(cfr[i][j], afr[i], bfr[j], cfr[i][j]);
        }
        __syncthreads();
    }

    // epilogue: stage 32x32 per warp into Cs (overlaps As/Bs; all reads done)
    #pragma unroll
    for (int i = 0; i < 2; i++)
        #pragma unroll
        for (int j = 0; j < 2; j++)
            wmma::store_matrix_sync(&sm.Cs[wid][i * 16][j * 16], cfr[i][j], 36, wmma::mem_row_major);
    __syncwarp();

    int lcol = (lane & 7) * 4;            // 0..28
    int lrow = lane >> 3;                 // 0..3
    int cbase = col0 + wc * 32 + lcol;
    float4 bz = make_float4(0.f, 0.f, 0.f, 0.f);
    if (bias) bz = *(const float4*)(bias + cbase);
    #pragma unroll
    for (int it = 0; it < 8; it++) {
        int rr = it * 4 + lrow;           // 0..31
        int r = row0 + wr * 32 + rr;
        if (r >= M) continue;
        float4 v = *(float4*)&sm.Cs[wid][rr][lcol];
        float* cp = C + (size_t)r * N + cbase;
        v.x += bz.x; v.y += bz.y; v.z += bz.z; v.w += bz.w;
        if (flags & FLAG_RELU) {
            v.x = fmaxf(v.x, 0.f); v.y = fmaxf(v.y, 0.f);
            v.z = fmaxf(v.z, 0.f); v.w = fmaxf(v.w, 0.f);
        }
        *(float4*)cp = v;
    }
}

// ---------------- el = sum over dh of fs * a_l ----------------
__global__ void el_kernel(const float* __restrict__ a1l, const float* __restrict__ a2l) {
    int t = blockIdx.x * blockDim.x + threadIdx.x;
    if (t < NGT * NH) {
        int i = t >> 2, h = t & 3;
        const float* f = g_fs1 + (size_t)i * VIS + h * 16;
        const float* a = a1l + h * 16;
        float s = 0.f;
        #pragma unroll
        for (int d = 0; d < 16; d++) s += f[d] * a[d];
        g_el1[t] = s;
    } else if (t < 2 * NGT * NH) {
        int u = t - NGT * NH;
        int i = u >> 2, h = u & 3;
        const float* f = g_fs2 + (size_t)i * CMM + h * 32;
        const float* a = a2l + h * 32;
        float s = 0.f;
        #pragma unroll
        for (int d = 0; d < 32; d++) s += f[d] * a[d];
        g_el2[u] = s;
    }
}

// ---------------- global per-head max of el1/el2 ----------------
__global__ void gmax_kernel() {
    __shared__ unsigned s1[4], s2[4];
    int tid = threadIdx.x;
    if (tid < 4) { s1[tid] = 0u; s2[tid] = 0u; }
    __syncthreads();
    unsigned l1[4] = {0u, 0u, 0u, 0u}, l2[4] = {0u, 0u, 0u, 0u};
    for (int i = blockIdx.x * blockDim.x + tid; i < NGT; i += gridDim.x * blockDim.x) {
        float4 e1 = *(const float4*)&g_el1[i * 4];
        float4 e2 = *(const float4*)&g_el2[i * 4];
        l1[0] = max(l1[0], fkey(e1.x)); l1[1] = max(l1[1], fkey(e1.y));
        l1[2] = max(l1[2], fkey(e1.z)); l1[3] = max(l1[3], fkey(e1.w));
        l2[0] = max(l2[0], fkey(e2.x)); l2[1] = max(l2[1], fkey(e2.y));
        l2[2] = max(l2[2], fkey(e2.z)); l2[3] = max(l2[3], fkey(e2.w));
    }
    #pragma unroll
    for (int h = 0; h < 4; h++) { atomicMax(&s1[h], l1[h]); atomicMax(&s2[h], l2[h]); }
    __syncthreads();
    if (tid < 4) { atomicMax(&g_gmx1[tid], s1[tid]); atomicMax(&g_gmx2[tid], s2[tid]); }
}

// ---------------- er1 = feat_agent @ v1 ----------------
__global__ void er1_kernel(const float* __restrict__ feat_agent) {
    int t = blockIdx.x * blockDim.x + threadIdx.x;
    if (t >= NAG * NH) return;
    int n = t >> 2, h = t & 3;
    const float* f = feat_agent + (size_t)n * DAG;
    float s = 0.f;
    #pragma unroll 8
    for (int k = 0; k < DAG; k++) s += f[k] * g_v1[k * NH + h];
    g_er1[t] = s;
}

// ---------------- er2 = dst2 @ v2 ----------------
__global__ void er2_kernel() {
    int t = blockIdx.x * blockDim.x + threadIdx.x;
    if (t >= NAG * NH) return;
    int n = t >> 2, h = t & 3;
    const float* f = g_dst2 + (size_t)n * CMM;
    float s = 0.f;
    #pragma unroll 8
    for (int k = 0; k < CMM; k++) s += f[k] * g_v2[k * NH + h];
    g_er2[t] = s;
}

// ---------------- CSR build (merged launches) ----------------
__global__ void count2_kernel(const int* __restrict__ gt_dst, const int* __restrict__ cm_dst) {
    int e = blockIdx.x * blockDim.x + threadIdx.x;
    if (e < EGT) atomicAdd(&g_cnt_gt[gt_dst[e]], 1);
    else if (e < EGT + ECM) atomicAdd(&g_cnt_cm[cm_dst[e - EGT]], 1);
}

__device__ void scan_body(const int* __restrict__ cnt, int* __restrict__ offs, int n) {
    __shared__ int wsum[32];
    __shared__ int carry;
    int tid = threadIdx.x, lane = tid & 31, wid = tid >> 5;
    if (tid == 0) carry = 0;
    __syncthreads();
    for (int base = 0; base < n; base += 1024) {
        int i = base + tid;
        int v = (i < n) ? cnt[i] : 0;
        int x = v;
        #pragma unroll
        for (int off = 1; off < 32; off <<= 1) {
            int t = __shfl_up_sync(0xffffffffu, x, off);
            if (lane >= off) x += t;
        }
        if (lane == 31) wsum[wid] = x;
        __syncthreads();
        if (wid == 0) {
            int s = wsum[lane];
            #pragma unroll
            for (int off = 1; off < 32; off <<= 1) {
                int t = __shfl_up_sync(0xffffffffu, s, off);
                if (lane >= off) s += t;
            }
            wsum[lane] = s;
        }
        __syncthreads();
        int wpre = (wid > 0) ? wsum[wid - 1] : 0;
        int incl = carry + wpre + x;
        if (i < n) offs[i] = incl - v;
        __syncthreads();
        if (tid == 1023) carry = incl;
        __syncthreads();
    }
    if (tid == 0) offs[n] = carry;
}

__global__ void scan2_kernel() {
    if (blockIdx.x == 0) scan_body(g_cnt_gt, g_offs_gt, NAG);
    else                 scan_body(g_cnt_cm, g_offs_cm, NAG);
}

__global__ void scatter2_kernel(const int* __restrict__ gt_src, const int* __restrict__ gt_dst,
                                const int* __restrict__ cm_src, const int* __restrict__ cm_dst) {
    int e = blockIdx.x * blockDim.x + threadIdx.x;
    if (e < EGT) {
        int d = gt_dst[e];
        int p = atomicAdd(&g_cur_gt[d], 1);
        g_csr_gt[g_offs_gt[d] + p] = gt_src[e];
    } else if (e < EGT + ECM) {
        int e2 = e - EGT;
        int d = cm_dst[e2];
        int p = atomicAdd(&g_cur_cm[d], 1);
        g_csr_cm[g_offs_cm[d] + p] = cm_src[e2];
    }
}

// ---------------- GAT1: single-pass softmax via global shift (warp per dst) ----------------
__global__ void gat1_kernel(const float* __restrict__ feat_agent, const float* __restrict__ b1) {
    int w = (blockIdx.x * blockDim.x + threadIdx.x) >> 5;
    if (w >= NAG) return;
    int lane = threadIdx.x & 31;
    int beg = g_offs_gt[w], end = g_offs_gt[w + 1];
    float4 er = *(const float4*)&g_er1[w * 4];
    float m0 = lrelu(fdecode(g_gmx1[0]) + er.x);
    float m1 = lrelu(fdecode(g_gmx1[1]) + er.y);
    float m2 = lrelu(fdecode(g_gmx1[2]) + er.z);
    float m3 = lrelu(fdecode(g_gmx1[3]) + er.w);
    float d0 = 0.f, d1 = 0.f, d2 = 0.f, d3 = 0.f;
    float acc0 = 0.f, acc1 = 0.f;
    int hs = lane >> 4;
    for (int e = beg; e < end; e++) {
        int s = g_csr_gt[e];
        float4 el = *(const float4*)&g_el1[s * 4];
        float p0 = __expf(lrelu(el.x + er.x) - m0);
        float p1 = __expf(lrelu(el.y + er.y) - m1);
        float p2 = __expf(lrelu(el.z + er.z) - m2);
        float p3 = __expf(lrelu(el.w + er.w) - m3);
        d0 += p0; d1 += p1; d2 += p2; d3 += p3;
        float pa = (hs == 0) ? p0 : p1;
        float pb = (hs == 0) ? p2 : p3;
        const float* fr = g_fs1 + (size_t)s * VIS;
        acc0 += pa * fr[lane];
        acc1 += pb * fr[32 + lane];
    }
    float da = (hs == 0) ? d0 : d1;
    float db = (hs == 0) ? d2 : d3;
    float ia = da > 0.f ? 1.f / da : 0.f;
    float ib = db > 0.f ? 1.f / db : 0.f;
    float fa0 = feat_agent[(size_t)w * DAG + lane];
    float fa1 = feat_agent[(size_t)w * DAG + 32 + lane];
    float o0 = fmaxf(acc0 * ia + fa0 + b1[lane], 0.f);
    float o1 = fmaxf(acc1 * ib + fa1 + b1[32 + lane], 0.f);
    float* dr = g_dst2 + (size_t)w * CMM;
    dr[lane] = o0; dr[32 + lane] = o1;
    dr[64 + lane] = fa0; dr[96 + lane] = fa1;
}

// ---------------- GAT2: single-pass softmax via global shift ----------------
__global__ void gat2_kernel(const float* __restrict__ b2) {
    int w = (blockIdx.x * blockDim.x + threadIdx.x) >> 5;
    if (w >= NAG) return;
    int lane = threadIdx.x & 31;
    int beg = g_offs_gt[w], end = g_offs_gt[w + 1];
    float4 er = *(const float4*)&g_er2[w * 4];
    float m0 = lrelu(fdecode(g_gmx2[0]) + er.x);
    float m1 = lrelu(fdecode(g_gmx2[1]) + er.y);
    float m2 = lrelu(fdecode(g_gmx2[2]) + er.z);
    float m3 = lrelu(fdecode(g_gmx2[3]) + er.w);
    float d0 = 0.f, d1 = 0.f, d2 = 0.f, d3 = 0.f;
    float a0 = 0.f, a1 = 0.f, a2 = 0.f, a3 = 0.f;
    for (int e = beg; e < end; e++) {
        int s = g_csr_gt[e];
        float4 el = *(const float4*)&g_el2[s * 4];
        float p0 = __expf(lrelu(el.x + er.x) - m0);
        float p1 = __expf(lrelu(el.y + er.y) - m1);
        float p2 = __expf(lrelu(el.z + er.z) - m2);
        float p3 = __expf(lrelu(el.w + er.w) - m3);
        d0 += p0; d1 += p1; d2 += p2; d3 += p3;
        const float* fr = g_fs2 + (size_t)s * CMM;
        a0 += p0 * fr[lane];
        a1 += p1 * fr[32 + lane];
        a2 += p2 * fr[64 + lane];
        a3 += p3 * fr[96 + lane];
    }
    float i0 = d0 > 0.f ? 1.f / d0 : 0.f;
    float i1 = d1 > 0.f ? 1.f / d1 : 0.f;
    float i2 = d2 > 0.f ? 1.f / d2 : 0.f;
    float i3 = d3 > 0.f ? 1.f / d3 : 0.f;
    const float* dr = g_dst2 + (size_t)w * CMM;
    float* hr = g_h + (size_t)w * CMM;
    hr[lane]      = fmaxf(a0 * i0 + dr[lane]      + b2[lane],      0.f);
    hr[32 + lane] = fmaxf(a1 * i1 + dr[32 + lane] + b2[32 + lane], 0.f);
    hr[64 + lane] = fmaxf(a2 * i2 + dr[64 + lane] + b2[64 + lane], 0.f);
    hr[96 + lane] = fmaxf(a3 * i3 + dr[96 + lane] + b2[96 + lane], 0.f);
}

// ---------------- comm mailbox mean ----------------
__global__ void comm_agg_kernel() {
    int w = (blockIdx.x * blockDim.x + threadIdx.x) >> 5;
    if (w >= NAG) return;
    int lane = threadIdx.x & 31;
    int beg = g_offs_cm[w], end = g_offs_cm[w + 1];
    float a0 = 0.f, a1 = 0.f;
    for (int e = beg; e < end; e++) {
        int s = g_csr_cm[e];
        const float* mr = g_m + (size_t)s * MSG;
        a0 += mr[lane];
        a1 += mr[32 + lane];
    }
    int deg = end - beg;
    float inv = 1.f / (float)(deg > 0 ? deg : 1);
    g_y[(size_t)w * MSG + lane] = a0 * inv;
    g_y[(size_t)w * MSG + 32 + lane] = a1 * inv;
}

// ---------------- GRU elementwise combine ----------------
__global__ void gru_kernel(const float* __restrict__ zz) {
    int idx = blockIdx.x * blockDim.x + threadIdx.x;
    if (idx >= NAG * CMM) return;
    int n = idx >> 7, j = idx & 127;
    size_t base = (size_t)n * 384;
    float ir = g_gi[base + j],       hr = g_gh[base + j];
    float iz = g_gi[base + 128 + j], hz = g_gh[base + 128 + j];
    float in_ = g_gi[base + 256 + j], hn = g_gh[base + 256 + j];
    float r  = 1.f / (1.f + __expf(-(ir + hr)));
    float zg = 1.f / (1.f + __expf(-(iz + hz)));
    float nn = tanhf(in_ + r * hn);
    g_h[idx] = (1.f - zg) * nn + zg * zz[idx];
}

// ---------------- output head ----------------
__global__ void out_kernel(const float* __restrict__ W, const float* __restrict__ b,
                           float* __restrict__ out) {
    int idx = blockIdx.x * blockDim.x + threadIdx.x;
    if (idx >= NAG * OUTD) return;
    int n = idx / OUTD, j = idx % OUTD;
    const float* hr = g_h + (size_t)n * CMM;
    float s = b[j];
    #pragma unroll 8
    for (int k = 0; k < CMM; k++) s += hr[k] * W[k * OUTD + j];
    out[idx] = s;
}

// ---------------- host launch ----------------
static void gemm(const float* A, const float* B, const float* bias, float* C,
                 int M, int N, int K, int ldb, int flags) {
    dim3 grid((M + 63) / 64, N / 64);
    gemm_k<<<grid, 256>>>(A, B, bias, C, M, N, K, ldb, flags);
}

static void gemm_tf32(const float* A, const float* A2, const float* B, const float* bias,
                      float* C, int M, int N, int K1, int K2, int flags) {
    dim3 grid((M + 127) / 128, N / 64);
    gemm_tc<<<grid, 256>>>(A, A2, B, bias, C, M, N, K1, K2, flags);
}

extern "C" void kernel_launch(void* const* d_in, const int* in_sizes, int n_in,
                              void* d_out, int out_size) {
    const float* feat_gt    = (const float*)d_in[0];
    const float* feat_agent = (const float*)d_in[1];
    const float* z          = (const float*)d_in[2];
    const int*   gt_src     = (const int*)d_in[3];
    const int*   gt_dst     = (const int*)d_in[4];
    const int*   comm_src   = (const int*)d_in[5];
    const int*   comm_dst   = (const int*)d_in[6];
    const float* w1_src     = (const float*)d_in[7];
    const float* w1_dst     = (const float*)d_in[8];
    const float* a1_l       = (const float*)d_in[9];
    const float* a1_r       = (const float*)d_in[10];
    const float* b1         = (const float*)d_in[11];
    const float* w2_src     = (const float*)d_in[12];
    const float* w2_dst     = (const float*)d_in[13];
    const float* a2_l       = (const float*)d_in[14];
    const float* a2_r       = (const float*)d_in[15];
    const float* b2         = (const float*)d_in[16];
    const float* enc_w1     = (const float*)d_in[17];
    const float* enc_b1     = (const float*)d_in[18];
    const float* enc_w2     = (const float*)d_in[19];
    const float* enc_b2     = (const float*)d_in[20];
    const float* gw_ih      = (const float*)d_in[21];
    const float* gw_hh      = (const float*)d_in[22];
    const float* gb_ih      = (const float*)d_in[23];
    const float* gb_hh      = (const float*)d_in[24];
    const float* out_w      = (const float*)d_in[25];
    const float* out_b      = (const float*)d_in[26];

    float *p_fs1, *p_fs2, *p_h, *p_t, *p_m, *p_y, *p_gi, *p_gh;
    cudaGetSymbolAddress((void**)&p_fs1, g_fs1);
    cudaGetSymbolAddress((void**)&p_fs2, g_fs2);
    cudaGetSymbolAddress((void**)&p_h,   g_h);
    cudaGetSymbolAddress((void**)&p_t,   g_t128);
    cudaGetSymbolAddress((void**)&p_m,   g_m);
    cudaGetSymbolAddress((void**)&p_y,   g_y);
    cudaGetSymbolAddress((void**)&p_gi,  g_gi);
    cudaGetSymbolAddress((void**)&p_gh,  g_gh);

    // 1) init + folded dst-attention vectors
    init_kernel<<<(NAG + 255) / 256, 256>>>();
    v12_kernel<<<1, 256>>>(w1_dst, a1_r, w2_dst, a2_r);

    // 2) src projections (fp32 — feed attention scores)
    gemm(feat_gt, w1_src, nullptr, p_fs1, NGT, VIS, DGT, VIS, 0);
    gemm(feat_gt, w2_src, nullptr, p_fs2, NGT, CMM, DGT, CMM, 0);

    // 3) per-node attention scalars + global maxima
    el_kernel<<<(2 * NGT * NH + 255) / 256, 256>>>(a1_l, a2_l);
    gmax_kernel<<<296, 256>>>();
    er1_kernel<<<(NAG * NH + 255) / 256, 256>>>(feat_agent);

    // 4) CSR build for both edge lists (merged launches)
    count2_kernel<<<(EGT + ECM + 255) / 256, 256>>>(gt_dst, comm_dst);
    scan2_kernel<<<2, 1024>>>();
    scatter2_kernel<<<(EGT + ECM + 255) / 256, 256>>>(gt_src, gt_dst, comm_src, comm_dst);

    // 5) GAT stage 1 -> dst2, then stage 2 -> h (single-pass each)
    gat1_kernel<<<(NAG * 32 + 255) / 256, 256>>>(feat_agent, b1);
    er2_kernel<<<(NAG * NH + 255) / 256, 256>>>();
    gat2_kernel<<<(NAG * 32 + 255) / 256, 256>>>(b2);

    // 6) two comm steps (tf32 tensor-core GEMMs; gi fused over [h|y])
    const float* zz = z;
    for (int step = 0; step < 2; step++) {
        gemm_tf32(p_h, nullptr, enc_w1, enc_b1, p_t, NAG, 128, CMM, 0, FLAG_RELU);
        gemm_tf32(p_t, nullptr, enc_w2, enc_b2, p_m, NAG, MSG, 128, 0, FLAG_RELU);
        comm_agg_kernel<<<(NAG * 32 + 255) / 256, 256>>>();
        // gi = h @ W_ih[0:128] + y @ W_ih[128:192] + b_ih (single fused GEMM)
        gemm_tf32(p_h, p_y, gw_ih, gb_ih, p_gi, NAG, 384, CMM, MSG, 0);
        gemm_tf32(zz, nullptr, gw_hh, gb_hh, p_gh, NAG, 384, CMM, 0, 0);
        gru_kernel<<<(NAG * CMM + 255) / 256, 256>>>(zz);
        zz = p_h;   // after update, zz == h
    }

    // 7) outputs: (h_out [NAG,5], zz [NAG,128]) flattened in order
    float* out = (float*)d_out;
    if (out_size == NAG * CMM) {
        cudaMemcpyAsync(out, p_h, (size_t)NAG * CMM * sizeof(float), cudaMemcpyDeviceToDevice);
    } else if (out_size == NAG * OUTD) {
        out_kernel<<<(NAG * OUTD + 255) / 256, 256>>>(out_w, out_b, out);
    } else {
        out_kernel<<<(NAG * OUTD + 255) / 256, 256>>>(out_w, out_b, out);
        cudaMemcpyAsync(out + NAG * OUTD, p_h, (size_t)NAG * CMM * sizeof(float),
                        cudaMemcpyDeviceToDevice);
    }
}